// round 2
// baseline (speedup 1.0000x reference)
#include <cuda_runtime.h>
#include <math.h>

// Problem dims
#define M_ROWS  8192      // 4 * 2048
#define N_ATOMS 16384
#define DM      1024
#define NEG_INF (-1e9f)

// 512 MB scratch for scores / weights
__device__ float g_scores[(size_t)M_ROWS * N_ATOMS];

// ---------------------------------------------------------------------------
// K1: scores[m, a] = sum_k X[m,k] * Dict[a,k], then mask -> -1e9
// Tiling: 128x128 block tile, BK=8, 256 threads, 8x8 per thread.
// Both X and Dict are K-contiguous -> identical coalesced transpose loads.
// ---------------------------------------------------------------------------
__global__ __launch_bounds__(256) void scores_kernel(
    const float* __restrict__ X, const float* __restrict__ Dm,
    const int* __restrict__ mask, float* __restrict__ S)
{
    __shared__ float As[8][128];
    __shared__ float Bs[8][128];

    const int bm = blockIdx.y * 128;
    const int bn = blockIdx.x * 128;
    const int tid = threadIdx.x;

    const int lm = tid >> 1;            // row within tile for loading (0..127)
    const int lk = (tid & 1) * 4;       // k quad (0 or 4)

    const int tm = (tid >> 4) * 8;      // 16x16 thread grid, 8x8 micro-tile
    const int tn = (tid & 15) * 8;

    float acc[8][8];
    #pragma unroll
    for (int i = 0; i < 8; i++)
        #pragma unroll
        for (int j = 0; j < 8; j++) acc[i][j] = 0.0f;

    const float* aptr = X  + (size_t)(bm + lm) * DM + lk;
    const float* bptr = Dm + (size_t)(bn + lm) * DM + lk;

    for (int k0 = 0; k0 < DM; k0 += 8) {
        float4 av = *reinterpret_cast<const float4*>(aptr + k0);
        float4 bv = *reinterpret_cast<const float4*>(bptr + k0);
        __syncthreads();
        As[lk + 0][lm] = av.x; As[lk + 1][lm] = av.y;
        As[lk + 2][lm] = av.z; As[lk + 3][lm] = av.w;
        Bs[lk + 0][lm] = bv.x; Bs[lk + 1][lm] = bv.y;
        Bs[lk + 2][lm] = bv.z; Bs[lk + 3][lm] = bv.w;
        __syncthreads();

        #pragma unroll
        for (int k = 0; k < 8; k++) {
            float a[8], b[8];
            #pragma unroll
            for (int i = 0; i < 8; i++) a[i] = As[k][tm + i];
            #pragma unroll
            for (int j = 0; j < 8; j++) b[j] = Bs[k][tn + j];
            #pragma unroll
            for (int i = 0; i < 8; i++)
                #pragma unroll
                for (int j = 0; j < 8; j++)
                    acc[i][j] = fmaf(a[i], b[j], acc[i][j]);
        }
    }

    // Epilogue: apply mask, write scores
    #pragma unroll
    for (int i = 0; i < 8; i++) {
        const size_t row = (size_t)(bm + tm + i);
        #pragma unroll
        for (int j = 0; j < 8; j += 4) {
            const size_t col = (size_t)(bn + tn + j);
            int4 mv = *reinterpret_cast<const int4*>(&mask[row * N_ATOMS + col]);
            float4 ov;
            ov.x = mv.x ? acc[i][j + 0] : NEG_INF;
            ov.y = mv.y ? acc[i][j + 1] : NEG_INF;
            ov.z = mv.z ? acc[i][j + 2] : NEG_INF;
            ov.w = mv.w ? acc[i][j + 3] : NEG_INF;
            *reinterpret_cast<float4*>(&S[row * N_ATOMS + col]) = ov;
        }
    }
}

// ---------------------------------------------------------------------------
// K2: per-row max+argmax (first-occurrence ties like jnp.argmax), then
// softmax in place. One block (256 threads) per row of 16384.
// ---------------------------------------------------------------------------
__global__ __launch_bounds__(256) void softmax_argmax_kernel(
    float* __restrict__ S, float* __restrict__ argmax_out)
{
    const int row = blockIdx.x;
    float* s = S + (size_t)row * N_ATOMS;
    const int tid = threadIdx.x;

    __shared__ float sv[256];
    __shared__ int   si[256];

    // Pass 1: max + argmax (strict > keeps smallest index per thread;
    // reduction tie-breaks to smaller index)
    float best = -INFINITY; int besti = 0;
    for (int c0 = tid * 4; c0 < N_ATOMS; c0 += 1024) {
        float4 v = *reinterpret_cast<const float4*>(s + c0);
        if (v.x > best) { best = v.x; besti = c0 + 0; }
        if (v.y > best) { best = v.y; besti = c0 + 1; }
        if (v.z > best) { best = v.z; besti = c0 + 2; }
        if (v.w > best) { best = v.w; besti = c0 + 3; }
    }
    sv[tid] = best; si[tid] = besti;
    __syncthreads();
    for (int off = 128; off > 0; off >>= 1) {
        if (tid < off) {
            float ov = sv[tid + off]; int oi = si[tid + off];
            if (ov > sv[tid] || (ov == sv[tid] && oi < si[tid])) {
                sv[tid] = ov; si[tid] = oi;
            }
        }
        __syncthreads();
    }
    const float rmax = sv[0];
    if (tid == 0) argmax_out[row] = (float)si[0];
    __syncthreads();

    // Pass 2: sum of exp
    float lsum = 0.0f;
    for (int c0 = tid * 4; c0 < N_ATOMS; c0 += 1024) {
        float4 v = *reinterpret_cast<const float4*>(s + c0);
        lsum += expf(v.x - rmax) + expf(v.y - rmax)
              + expf(v.z - rmax) + expf(v.w - rmax);
    }
    sv[tid] = lsum;
    __syncthreads();
    for (int off = 128; off > 0; off >>= 1) {
        if (tid < off) sv[tid] += sv[tid + off];
        __syncthreads();
    }
    const float inv = 1.0f / sv[0];

    // Pass 3: write normalized weights in place
    for (int c0 = tid * 4; c0 < N_ATOMS; c0 += 1024) {
        float4 v = *reinterpret_cast<float4*>(s + c0);
        v.x = expf(v.x - rmax) * inv;
        v.y = expf(v.y - rmax) * inv;
        v.z = expf(v.z - rmax) * inv;
        v.w = expf(v.w - rmax) * inv;
        *reinterpret_cast<float4*>(s + c0) = v;
    }
}

// ---------------------------------------------------------------------------
// K3: recon[m, d] = sum_a W[m,a] * Dict[a,d]
// W is K-contiguous (transpose load like K1's A); Dict is N-contiguous here.
// ---------------------------------------------------------------------------
__global__ __launch_bounds__(256) void recon_kernel(
    const float* __restrict__ W, const float* __restrict__ Dm,
    float* __restrict__ O)
{
    __shared__ float As[8][128];
    __shared__ float Bs[8][128];

    const int bm = blockIdx.y * 128;
    const int bn = blockIdx.x * 128;
    const int tid = threadIdx.x;

    const int lm = tid >> 1;
    const int lk = (tid & 1) * 4;

    const int bk = tid >> 5;            // 0..7 : k-row for B load
    const int bn4 = (tid & 31) * 4;     // 0..124 : n quad for B load

    const int tm = (tid >> 4) * 8;
    const int tn = (tid & 15) * 8;

    float acc[8][8];
    #pragma unroll
    for (int i = 0; i < 8; i++)
        #pragma unroll
        for (int j = 0; j < 8; j++) acc[i][j] = 0.0f;

    const float* aptr = W + (size_t)(bm + lm) * N_ATOMS + lk;

    for (int k0 = 0; k0 < N_ATOMS; k0 += 8) {
        float4 av = *reinterpret_cast<const float4*>(aptr + k0);
        float4 bv = *reinterpret_cast<const float4*>(
            &Dm[(size_t)(k0 + bk) * DM + bn + bn4]);
        __syncthreads();
        As[lk + 0][lm] = av.x; As[lk + 1][lm] = av.y;
        As[lk + 2][lm] = av.z; As[lk + 3][lm] = av.w;
        *reinterpret_cast<float4*>(&Bs[bk][bn4]) = bv;
        __syncthreads();

        #pragma unroll
        for (int k = 0; k < 8; k++) {
            float a[8], b[8];
            #pragma unroll
            for (int i = 0; i < 8; i++) a[i] = As[k][tm + i];
            #pragma unroll
            for (int j = 0; j < 8; j++) b[j] = Bs[k][tn + j];
            #pragma unroll
            for (int i = 0; i < 8; i++)
                #pragma unroll
                for (int j = 0; j < 8; j++)
                    acc[i][j] = fmaf(a[i], b[j], acc[i][j]);
        }
    }

    #pragma unroll
    for (int i = 0; i < 8; i++) {
        const size_t row = (size_t)(bm + tm + i);
        #pragma unroll
        for (int j = 0; j < 8; j += 4) {
            float4 ov = make_float4(acc[i][j], acc[i][j + 1],
                                    acc[i][j + 2], acc[i][j + 3]);
            *reinterpret_cast<float4*>(&O[row * DM + bn + tn + j]) = ov;
        }
    }
}

// ---------------------------------------------------------------------------
// Launch: X [8192,1024] f32, Dict [16384,1024] f32, mask [8192,16384] i32.
// Output: recon (8192*1024 f32) followed by argmax indices as f32 (8192).
// ---------------------------------------------------------------------------
extern "C" void kernel_launch(void* const* d_in, const int* in_sizes, int n_in,
                              void* d_out, int out_size)
{
    const float* X    = (const float*)d_in[0];
    const float* Dict = (const float*)d_in[1];
    const int*   mask = (const int*)d_in[2];
    float* out = (float*)d_out;

    float* scores = nullptr;
    cudaGetSymbolAddress((void**)&scores, g_scores);

    float* recon_out  = out;
    float* argmax_out = out + (size_t)M_ROWS * DM;

    {
        dim3 grid(N_ATOMS / 128, M_ROWS / 128);
        scores_kernel<<<grid, 256>>>(X, Dict, mask, scores);
    }
    {
        softmax_argmax_kernel<<<M_ROWS, 256>>>(scores, argmax_out);
    }
    {
        dim3 grid(DM / 128, M_ROWS / 128);
        recon_kernel<<<grid, 256>>>(scores, Dict, recon_out);
    }
}

// round 4
// speedup vs baseline: 2.6410x; 2.6410x over previous
#include <cuda_runtime.h>
#include <cuda_bf16.h>
#include <math.h>
#include <stdint.h>

// ---------------------------------------------------------------------------
// Problem dims
// ---------------------------------------------------------------------------
#define M_ROWS  8192      // 4 * 2048
#define N_ATOMS 16384
#define DM      1024
#define NEG_INF (-1e9f)

// ---------------------------------------------------------------------------
// Scratch (__device__ globals; allocation APIs are forbidden)
// ---------------------------------------------------------------------------
__device__ float          g_scores[(size_t)M_ROWS * N_ATOMS];        // 512 MB
__device__ __nv_bfloat16  g_Xh[(size_t)M_ROWS * DM];
__device__ __nv_bfloat16  g_Xl[(size_t)M_ROWS * DM];
__device__ __nv_bfloat16  g_Dh[(size_t)N_ATOMS * DM];
__device__ __nv_bfloat16  g_Dl[(size_t)N_ATOMS * DM];
__device__ __nv_bfloat16  g_DTh[(size_t)DM * N_ATOMS];               // dict^T
__device__ __nv_bfloat16  g_DTl[(size_t)DM * N_ATOMS];
__device__ __nv_bfloat16  g_Wh[(size_t)M_ROWS * N_ATOMS];            // 256 MB
__device__ __nv_bfloat16  g_Wl[(size_t)M_ROWS * N_ATOMS];            // 256 MB
__device__ int            g_top2[M_ROWS * 2];

// ---------------------------------------------------------------------------
// Low-level helpers (sm_80+ baseline PTX only — NO tcgen05 on plain sm_103)
// ---------------------------------------------------------------------------
__device__ __forceinline__ uint32_t smem_to_u32(const void* p) {
    uint32_t a;
    asm("{ .reg .u64 t; cvta.to.shared.u64 t, %1; cvt.u32.u64 %0, t; }"
        : "=r"(a) : "l"(p));
    return a;
}

#define CP16(dst, src) \
    asm volatile("cp.async.cg.shared.global [%0], [%1], 16;" \
                 :: "r"(dst), "l"(src) : "memory")
#define CP_COMMIT() asm volatile("cp.async.commit_group;" ::: "memory")
#define CP_WAIT0()  asm volatile("cp.async.wait_group 0;"  ::: "memory")

#define LDS32(v, a) \
    asm volatile("ld.shared.b32 %0, [%1];" : "=r"(v) : "r"(a))

__device__ __forceinline__ void mma16816(float* c, const uint32_t* a,
                                         const uint32_t* b) {
    asm volatile(
        "mma.sync.aligned.m16n8k16.row.col.f32.bf16.bf16.f32 "
        "{%0,%1,%2,%3}, {%4,%5,%6,%7}, {%8,%9}, {%0,%1,%2,%3};"
        : "+f"(c[0]), "+f"(c[1]), "+f"(c[2]), "+f"(c[3])
        : "r"(a[0]), "r"(a[1]), "r"(a[2]), "r"(a[3]), "r"(b[0]), "r"(b[1]));
}

// ---------------------------------------------------------------------------
// Conversion kernels: fp32 -> bf16 hi/lo split
// ---------------------------------------------------------------------------
__global__ __launch_bounds__(256) void split_hilo_kernel(
    const float* __restrict__ src, __nv_bfloat16* __restrict__ hi,
    __nv_bfloat16* __restrict__ lo, int n4)
{
    int i = blockIdx.x * blockDim.x + threadIdx.x;
    if (i >= n4) return;
    float4 v = reinterpret_cast<const float4*>(src)[i];
    __nv_bfloat16 h0 = __float2bfloat16(v.x);
    __nv_bfloat16 h1 = __float2bfloat16(v.y);
    __nv_bfloat16 h2 = __float2bfloat16(v.z);
    __nv_bfloat16 h3 = __float2bfloat16(v.w);
    ushort4 hv, lv;
    hv.x = __bfloat16_as_ushort(h0); hv.y = __bfloat16_as_ushort(h1);
    hv.z = __bfloat16_as_ushort(h2); hv.w = __bfloat16_as_ushort(h3);
    lv.x = __bfloat16_as_ushort(__float2bfloat16(v.x - __bfloat162float(h0)));
    lv.y = __bfloat16_as_ushort(__float2bfloat16(v.y - __bfloat162float(h1)));
    lv.z = __bfloat16_as_ushort(__float2bfloat16(v.z - __bfloat162float(h2)));
    lv.w = __bfloat16_as_ushort(__float2bfloat16(v.w - __bfloat162float(h3)));
    reinterpret_cast<ushort4*>(hi)[i] = hv;
    reinterpret_cast<ushort4*>(lo)[i] = lv;
}

// dict [N_ATOMS][DM] fp32 -> DT hi/lo [DM][N_ATOMS] bf16
__global__ __launch_bounds__(256) void transpose_split_kernel(
    const float* __restrict__ dict, __nv_bfloat16* __restrict__ DTh,
    __nv_bfloat16* __restrict__ DTl)
{
    __shared__ float t[32][33];
    const int bx = blockIdx.x;   // DM tile
    const int by = blockIdx.y;   // atom tile
    const int tx = threadIdx.x;  // 0..31
    const int ty = threadIdx.y;  // 0..7
    #pragma unroll
    for (int k = 0; k < 32; k += 8)
        t[ty + k][tx] = dict[(size_t)(by * 32 + ty + k) * DM + bx * 32 + tx];
    __syncthreads();
    #pragma unroll
    for (int k = 0; k < 32; k += 8) {
        float v = t[tx][ty + k];
        size_t o = (size_t)(bx * 32 + ty + k) * N_ATOMS + by * 32 + tx;
        __nv_bfloat16 h = __float2bfloat16(v);
        DTh[o] = h;
        DTl[o] = __float2bfloat16(v - __bfloat162float(h));
    }
}

// ---------------------------------------------------------------------------
// Split-bf16 GEMM on legacy tensor cores (mma.sync m16n8k16):
//   out[128x128 tile] += Ah·Bh^T + Ah·Bl^T + Al·Bh^T   (ll term dropped)
// A: [Mtot][Kdim] bf16 K-major; B: [Ntot][Kdim] bf16 K-major.
// mask != null: masked positions -> NEG_INF. out row stride = out_ld.
// 256 threads = 8 warps (2 m x 4 n), warp tile 64x32, BK=32, cp.async 2-stage.
// ---------------------------------------------------------------------------
#define BK          32
#define ROWB        80                    // 64B data + 16B pad per smem row
#define TILE_BYTES  (128 * ROWB)          // 10240
#define STAGE_BYTES (4 * TILE_BYTES)      // 40960 (Ah, Al, Bh, Bl)
#define GEMM_SMEM   (2 * STAGE_BYTES)     // 81920

__global__ __launch_bounds__(256, 2) void gemm_split_mma(
    const __nv_bfloat16* __restrict__ Ah, const __nv_bfloat16* __restrict__ Al,
    const __nv_bfloat16* __restrict__ Bh, const __nv_bfloat16* __restrict__ Bl,
    int Kdim, const int* __restrict__ mask, float* __restrict__ out, int out_ld)
{
    extern __shared__ char smem[];
    const uint32_t sbase = smem_to_u32(smem);
    const int tid  = threadIdx.x;
    const int warp = tid >> 5;
    const int lane = tid & 31;
    const int bm = blockIdx.y * 128;
    const int bn = blockIdx.x * 128;

    const int wm = (warp & 1) * 64;   // warp m offset
    const int wn = (warp >> 1) * 32;  // warp n offset

    float acc[4][4][4];
    #pragma unroll
    for (int mt = 0; mt < 4; mt++)
        #pragma unroll
        for (int nt = 0; nt < 4; nt++)
            #pragma unroll
            for (int r = 0; r < 4; r++) acc[mt][nt][r] = 0.0f;

    const int NC = Kdim >> 5;  // BK=32 chunks

    // ---- async load of one chunk into stage buf ----
    #define ISSUE(cc, buf) do { \
        const int k0_ = (cc) << 5; \
        _Pragma("unroll") \
        for (int p = 0; p < 2; p++) { \
            const int v_   = tid + p * 256; \
            const int row_ = v_ >> 2; \
            const int c16_ = v_ & 3; \
            const uint32_t dst_ = sbase + (buf) * STAGE_BYTES \
                                + row_ * ROWB + c16_ * 16; \
            const size_t ga_ = (size_t)(bm + row_) * Kdim + k0_ + c16_ * 8; \
            const size_t gb_ = (size_t)(bn + row_) * Kdim + k0_ + c16_ * 8; \
            CP16(dst_ + 0 * TILE_BYTES, Ah + ga_); \
            CP16(dst_ + 1 * TILE_BYTES, Al + ga_); \
            CP16(dst_ + 2 * TILE_BYTES, Bh + gb_); \
            CP16(dst_ + 3 * TILE_BYTES, Bl + gb_); \
        } \
        CP_COMMIT(); \
    } while (0)

    ISSUE(0, 0);

    const int lr  = lane >> 2;        // 0..7
    const int lc4 = (lane & 3) * 4;   // byte offset of k-pair

    for (int c = 0; c < NC; c++) {
        CP_WAIT0();
        __syncthreads();
        if (c + 1 < NC) ISSUE(c + 1, (c + 1) & 1);

        const uint32_t sA_h = sbase + (c & 1) * STAGE_BYTES;
        const uint32_t sA_l = sA_h + TILE_BYTES;
        const uint32_t sB_h = sA_h + 2 * TILE_BYTES;
        const uint32_t sB_l = sA_h + 3 * TILE_BYTES;

        #pragma unroll
        for (int ks = 0; ks < 2; ks++) {
            const uint32_t kb = ks * 32 + lc4;

            uint32_t ah[4][4], al[4][4], bh[4][2], bl[4][2];
            #pragma unroll
            for (int mt = 0; mt < 4; mt++) {
                const uint32_t r0 = sA_h + (wm + mt * 16 + lr) * ROWB + kb;
                LDS32(ah[mt][0], r0);
                LDS32(ah[mt][1], r0 + 8 * ROWB);
                LDS32(ah[mt][2], r0 + 16);
                LDS32(ah[mt][3], r0 + 8 * ROWB + 16);
            }
            #pragma unroll
            for (int nt = 0; nt < 4; nt++) {
                const uint32_t r0 = sB_h + (wn + nt * 8 + lr) * ROWB + kb;
                LDS32(bh[nt][0], r0);
                LDS32(bh[nt][1], r0 + 16);
            }
            // term 1: Ah x Bh
            #pragma unroll
            for (int mt = 0; mt < 4; mt++)
                #pragma unroll
                for (int nt = 0; nt < 4; nt++)
                    mma16816(acc[mt][nt], ah[mt], bh[nt]);

            // term 2: Ah x Bl
            #pragma unroll
            for (int nt = 0; nt < 4; nt++) {
                const uint32_t r0 = sB_l + (wn + nt * 8 + lr) * ROWB + kb;
                LDS32(bl[nt][0], r0);
                LDS32(bl[nt][1], r0 + 16);
            }
            #pragma unroll
            for (int mt = 0; mt < 4; mt++)
                #pragma unroll
                for (int nt = 0; nt < 4; nt++)
                    mma16816(acc[mt][nt], ah[mt], bl[nt]);

            // term 3: Al x Bh
            #pragma unroll
            for (int mt = 0; mt < 4; mt++) {
                const uint32_t r0 = sA_l + (wm + mt * 16 + lr) * ROWB + kb;
                LDS32(al[mt][0], r0);
                LDS32(al[mt][1], r0 + 8 * ROWB);
                LDS32(al[mt][2], r0 + 16);
                LDS32(al[mt][3], r0 + 8 * ROWB + 16);
            }
            #pragma unroll
            for (int mt = 0; mt < 4; mt++)
                #pragma unroll
                for (int nt = 0; nt < 4; nt++)
                    mma16816(acc[mt][nt], al[mt], bh[nt]);
        }
        __syncthreads();
    }
    #undef ISSUE

    // ---- epilogue: optional mask, write fp32 ----
    #pragma unroll
    for (int mt = 0; mt < 4; mt++) {
        #pragma unroll
        for (int half = 0; half < 2; half++) {
            const size_t rg = (size_t)(bm + wm + mt * 16 + lr + half * 8);
            #pragma unroll
            for (int nt = 0; nt < 4; nt++) {
                const size_t o = rg * (size_t)out_ld
                               + (bn + wn + nt * 8 + (lane & 3) * 2);
                float2 v;
                v.x = acc[mt][nt][half * 2 + 0];
                v.y = acc[mt][nt][half * 2 + 1];
                if (mask) {
                    int2 mv = *reinterpret_cast<const int2*>(mask + o);
                    if (!mv.x) v.x = NEG_INF;
                    if (!mv.y) v.y = NEG_INF;
                }
                *reinterpret_cast<float2*>(out + o) = v;
            }
        }
    }
}

// ---------------------------------------------------------------------------
// Softmax + approximate top-2 per row; writes weights as bf16 hi/lo split.
// ---------------------------------------------------------------------------
__global__ __launch_bounds__(256) void softmax_top2_kernel(
    const float* __restrict__ S, __nv_bfloat16* __restrict__ Wh,
    __nv_bfloat16* __restrict__ Wl, int* __restrict__ top2)
{
    const int row = blockIdx.x;
    const float* s = S + (size_t)row * N_ATOMS;
    const int tid = threadIdx.x;

    __shared__ float sv1[256], sv2[256];
    __shared__ int   si1[256], si2[256];

    float v1 = -INFINITY, v2 = -INFINITY;
    int   i1 = 0x7fffffff, i2 = 0x7fffffff;

    #define INSERT(v, i) do { \
        if ((v) > v1 || ((v) == v1 && (i) < i1)) { \
            v2 = v1; i2 = i1; v1 = (v); i1 = (i); \
        } else if ((v) > v2 || ((v) == v2 && (i) < i2)) { \
            v2 = (v); i2 = (i); \
        } \
    } while (0)

    for (int c0 = tid * 4; c0 < N_ATOMS; c0 += 1024) {
        float4 v = *reinterpret_cast<const float4*>(s + c0);
        INSERT(v.x, c0 + 0); INSERT(v.y, c0 + 1);
        INSERT(v.z, c0 + 2); INSERT(v.w, c0 + 3);
    }
    sv1[tid] = v1; si1[tid] = i1; sv2[tid] = v2; si2[tid] = i2;
    __syncthreads();
    for (int off = 128; off > 0; off >>= 1) {
        if (tid < off) {
            v1 = sv1[tid]; i1 = si1[tid]; v2 = sv2[tid]; i2 = si2[tid];
            float ov1 = sv1[tid + off], ov2 = sv2[tid + off];
            int   oi1 = si1[tid + off], oi2 = si2[tid + off];
            INSERT(ov1, oi1); INSERT(ov2, oi2);
            sv1[tid] = v1; si1[tid] = i1; sv2[tid] = v2; si2[tid] = i2;
        }
        __syncthreads();
    }
    #undef INSERT

    const float rmax = sv1[0];
    if (tid == 0) { top2[row * 2] = si1[0]; top2[row * 2 + 1] = si2[0]; }
    __syncthreads();

    float lsum = 0.0f;
    for (int c0 = tid * 4; c0 < N_ATOMS; c0 += 1024) {
        float4 v = *reinterpret_cast<const float4*>(s + c0);
        lsum += expf(v.x - rmax) + expf(v.y - rmax)
              + expf(v.z - rmax) + expf(v.w - rmax);
    }
    sv1[tid] = lsum;
    __syncthreads();
    for (int off = 128; off > 0; off >>= 1) {
        if (tid < off) sv1[tid] += sv1[tid + off];
        __syncthreads();
    }
    const float inv = 1.0f / sv1[0];

    __nv_bfloat16* wh = Wh + (size_t)row * N_ATOMS;
    __nv_bfloat16* wl = Wl + (size_t)row * N_ATOMS;
    for (int c0 = tid * 4; c0 < N_ATOMS; c0 += 1024) {
        float4 v = *reinterpret_cast<const float4*>(s + c0);
        float w0 = expf(v.x - rmax) * inv;
        float w1 = expf(v.y - rmax) * inv;
        float w2 = expf(v.z - rmax) * inv;
        float w3 = expf(v.w - rmax) * inv;
        __nv_bfloat16 h0 = __float2bfloat16(w0), h1 = __float2bfloat16(w1);
        __nv_bfloat16 h2 = __float2bfloat16(w2), h3 = __float2bfloat16(w3);
        ushort4 hv, lv;
        hv.x = __bfloat16_as_ushort(h0); hv.y = __bfloat16_as_ushort(h1);
        hv.z = __bfloat16_as_ushort(h2); hv.w = __bfloat16_as_ushort(h3);
        lv.x = __bfloat16_as_ushort(__float2bfloat16(w0 - __bfloat162float(h0)));
        lv.y = __bfloat16_as_ushort(__float2bfloat16(w1 - __bfloat162float(h1)));
        lv.z = __bfloat16_as_ushort(__float2bfloat16(w2 - __bfloat162float(h2)));
        lv.w = __bfloat16_as_ushort(__float2bfloat16(w3 - __bfloat162float(h3)));
        *reinterpret_cast<ushort4*>(wh + c0) = hv;
        *reinterpret_cast<ushort4*>(wl + c0) = lv;
    }
}

// ---------------------------------------------------------------------------
// Exact fp32 argmax rescue: recompute the 2 candidate dot products per row.
// ---------------------------------------------------------------------------
__global__ __launch_bounds__(256) void argmax_rescue_kernel(
    const float* __restrict__ X, const float* __restrict__ Dict,
    const int* __restrict__ top2, float* __restrict__ argmax_out)
{
    const int row = blockIdx.x * 8 + (threadIdx.x >> 5);
    const int lid = threadIdx.x & 31;
    const int i1 = top2[row * 2];
    const int i2 = top2[row * 2 + 1];
    const float* x  = X + (size_t)row * DM;
    const float* d1 = Dict + (size_t)i1 * DM;
    const float* d2 = Dict + (size_t)i2 * DM;

    float s1 = 0.0f, s2 = 0.0f;
    for (int k = lid * 4; k < DM; k += 128) {
        float4 xv = *reinterpret_cast<const float4*>(x + k);
        float4 a  = *reinterpret_cast<const float4*>(d1 + k);
        float4 b  = *reinterpret_cast<const float4*>(d2 + k);
        s1 += xv.x * a.x + xv.y * a.y + xv.z * a.z + xv.w * a.w;
        s2 += xv.x * b.x + xv.y * b.y + xv.z * b.z + xv.w * b.w;
    }
    #pragma unroll
    for (int off = 16; off > 0; off >>= 1) {
        s1 += __shfl_xor_sync(0xffffffffu, s1, off);
        s2 += __shfl_xor_sync(0xffffffffu, s2, off);
    }
    if (lid == 0) {
        int best = (s1 > s2 || (s1 == s2 && i1 < i2)) ? i1 : i2;
        argmax_out[row] = (float)best;
    }
}

// ---------------------------------------------------------------------------
// Launch
// ---------------------------------------------------------------------------
extern "C" void kernel_launch(void* const* d_in, const int* in_sizes, int n_in,
                              void* d_out, int out_size)
{
    const float* X    = (const float*)d_in[0];
    const float* Dict = (const float*)d_in[1];
    const int*   mask = (const int*)d_in[2];
    float* out = (float*)d_out;

    float* scores; cudaGetSymbolAddress((void**)&scores, g_scores);
    __nv_bfloat16 *Xh, *Xl, *Dh, *Dl, *DTh, *DTl, *Wh, *Wl;
    cudaGetSymbolAddress((void**)&Xh, g_Xh);
    cudaGetSymbolAddress((void**)&Xl, g_Xl);
    cudaGetSymbolAddress((void**)&Dh, g_Dh);
    cudaGetSymbolAddress((void**)&Dl, g_Dl);
    cudaGetSymbolAddress((void**)&DTh, g_DTh);
    cudaGetSymbolAddress((void**)&DTl, g_DTl);
    cudaGetSymbolAddress((void**)&Wh, g_Wh);
    cudaGetSymbolAddress((void**)&Wl, g_Wl);
    int* top2; cudaGetSymbolAddress((void**)&top2, g_top2);

    float* recon_out  = out;
    float* argmax_out = out + (size_t)M_ROWS * DM;

    static bool attr_set = false;
    if (!attr_set) {
        cudaFuncSetAttribute(gemm_split_mma,
                             cudaFuncAttributeMaxDynamicSharedMemorySize,
                             GEMM_SMEM);
        attr_set = true;
    }

    // 1) hi/lo splits of X and dict (K-major) + transposed dict
    {
        int n4x = (M_ROWS * DM) / 4;
        split_hilo_kernel<<<(n4x + 255) / 256, 256>>>(X, Xh, Xl, n4x);
        int n4d = (N_ATOMS * DM) / 4;
        split_hilo_kernel<<<(n4d + 255) / 256, 256>>>(Dict, Dh, Dl, n4d);
        dim3 grid(DM / 32, N_ATOMS / 32), blk(32, 8);
        transpose_split_kernel<<<grid, blk>>>(Dict, DTh, DTl);
    }

    // 2) scores = X · dict^T with fused mask (tensor cores, 3-term split)
    {
        dim3 grid(N_ATOMS / 128, M_ROWS / 128);
        gemm_split_mma<<<grid, 256, GEMM_SMEM>>>(
            Xh, Xl, Dh, Dl, DM, mask, scores, N_ATOMS);
    }

    // 3) softmax + approx top-2, weights -> bf16 hi/lo
    softmax_top2_kernel<<<M_ROWS, 256>>>(scores, Wh, Wl, top2);

    // 4) exact fp32 argmax among the two candidates
    argmax_rescue_kernel<<<M_ROWS / 8, 256>>>(X, Dict, top2, argmax_out);

    // 5) reconstruction = W · dict (tensor cores, 3-term split)
    {
        dim3 grid(DM / 128, M_ROWS / 128);
        gemm_split_mma<<<grid, 256, GEMM_SMEM>>>(
            Wh, Wl, DTh, DTl, N_ATOMS, nullptr, recon_out, DM);
    }
}

// round 6
// speedup vs baseline: 3.9850x; 1.5089x over previous
#include <cuda_runtime.h>
#include <cuda_bf16.h>
#include <cuda_fp16.h>
#include <math.h>
#include <stdint.h>

// ---------------------------------------------------------------------------
// Problem dims
// ---------------------------------------------------------------------------
#define M_ROWS  8192      // 4 * 2048
#define N_ATOMS 16384
#define DM      1024
#define LOG2E   1.4426950408889634f
#define NEG_SCALED (-1.4426950e9f)   // NEG_INF * log2e

// ---------------------------------------------------------------------------
// Scratch (__device__ globals; allocation APIs are forbidden)
// ---------------------------------------------------------------------------
__device__ float          g_scores[(size_t)M_ROWS * N_ATOMS];        // 512 MB
__device__ __nv_bfloat16  g_Xh[(size_t)M_ROWS * DM];
__device__ __nv_bfloat16  g_Xl[(size_t)M_ROWS * DM];
__device__ __nv_bfloat16  g_Dh[(size_t)N_ATOMS * DM];
__device__ __nv_bfloat16  g_Dl[(size_t)N_ATOMS * DM];
__device__ __half         g_DTf[(size_t)DM * N_ATOMS];               // dict^T fp16
__device__ __half         g_Wf[(size_t)M_ROWS * N_ATOMS];            // 256 MB fp16
__device__ float          g_inv[M_ROWS];
__device__ int            g_top2[M_ROWS * 2];

// ---------------------------------------------------------------------------
// Low-level helpers (sm_80+ baseline PTX only — NO tcgen05 on plain sm_103)
// ---------------------------------------------------------------------------
__device__ __forceinline__ uint32_t smem_to_u32(const void* p) {
    uint32_t a;
    asm("{ .reg .u64 t; cvta.to.shared.u64 t, %1; cvt.u32.u64 %0, t; }"
        : "=r"(a) : "l"(p));
    return a;
}

#define CP16(dst, src) \
    asm volatile("cp.async.cg.shared.global [%0], [%1], 16;" \
                 :: "r"(dst), "l"(src) : "memory")
#define CP_COMMIT() asm volatile("cp.async.commit_group;" ::: "memory")
#define CP_WAIT0()  asm volatile("cp.async.wait_group 0;"  ::: "memory")

#define LDS32(v, a) \
    asm volatile("ld.shared.b32 %0, [%1];" : "=r"(v) : "r"(a))

__device__ __forceinline__ void mma16816_bf16(float* c, const uint32_t* a,
                                              const uint32_t* b) {
    asm volatile(
        "mma.sync.aligned.m16n8k16.row.col.f32.bf16.bf16.f32 "
        "{%0,%1,%2,%3}, {%4,%5,%6,%7}, {%8,%9}, {%0,%1,%2,%3};"
        : "+f"(c[0]), "+f"(c[1]), "+f"(c[2]), "+f"(c[3])
        : "r"(a[0]), "r"(a[1]), "r"(a[2]), "r"(a[3]), "r"(b[0]), "r"(b[1]));
}

__device__ __forceinline__ void mma16816_f16(float* c, const uint32_t* a,
                                             const uint32_t* b) {
    asm volatile(
        "mma.sync.aligned.m16n8k16.row.col.f32.f16.f16.f32 "
        "{%0,%1,%2,%3}, {%4,%5,%6,%7}, {%8,%9}, {%0,%1,%2,%3};"
        : "+f"(c[0]), "+f"(c[1]), "+f"(c[2]), "+f"(c[3])
        : "r"(a[0]), "r"(a[1]), "r"(a[2]), "r"(a[3]), "r"(b[0]), "r"(b[1]));
}

__device__ __forceinline__ float ex2f(float x) {
    float y;
    asm("ex2.approx.ftz.f32 %0, %1;" : "=f"(y) : "f"(x));
    return y;
}

// ---------------------------------------------------------------------------
// Conversion kernels
// ---------------------------------------------------------------------------
__global__ __launch_bounds__(256) void split_hilo_kernel(
    const float* __restrict__ src, __nv_bfloat16* __restrict__ hi,
    __nv_bfloat16* __restrict__ lo, int n4)
{
    int i = blockIdx.x * blockDim.x + threadIdx.x;
    if (i >= n4) return;
    float4 v = reinterpret_cast<const float4*>(src)[i];
    __nv_bfloat16 h0 = __float2bfloat16(v.x);
    __nv_bfloat16 h1 = __float2bfloat16(v.y);
    __nv_bfloat16 h2 = __float2bfloat16(v.z);
    __nv_bfloat16 h3 = __float2bfloat16(v.w);
    ushort4 hv, lv;
    hv.x = __bfloat16_as_ushort(h0); hv.y = __bfloat16_as_ushort(h1);
    hv.z = __bfloat16_as_ushort(h2); hv.w = __bfloat16_as_ushort(h3);
    lv.x = __bfloat16_as_ushort(__float2bfloat16(v.x - __bfloat162float(h0)));
    lv.y = __bfloat16_as_ushort(__float2bfloat16(v.y - __bfloat162float(h1)));
    lv.z = __bfloat16_as_ushort(__float2bfloat16(v.z - __bfloat162float(h2)));
    lv.w = __bfloat16_as_ushort(__float2bfloat16(v.w - __bfloat162float(h3)));
    reinterpret_cast<ushort4*>(hi)[i] = hv;
    reinterpret_cast<ushort4*>(lo)[i] = lv;
}

// dict [N_ATOMS][DM] fp32 -> DTf [DM][N_ATOMS] fp16
__global__ __launch_bounds__(256) void transpose_f16_kernel(
    const float* __restrict__ dict, __half* __restrict__ DTf)
{
    __shared__ float t[32][33];
    const int bx = blockIdx.x;   // DM tile
    const int by = blockIdx.y;   // atom tile
    const int tx = threadIdx.x;  // 0..31
    const int ty = threadIdx.y;  // 0..7
    #pragma unroll
    for (int k = 0; k < 32; k += 8)
        t[ty + k][tx] = dict[(size_t)(by * 32 + ty + k) * DM + bx * 32 + tx];
    __syncthreads();
    #pragma unroll
    for (int k = 0; k < 32; k += 8) {
        size_t o = (size_t)(bx * 32 + ty + k) * N_ATOMS + by * 32 + tx;
        DTf[o] = __float2half_rn(t[tx][ty + k]);
    }
}

// ---------------------------------------------------------------------------
// Shared GEMM geometry: 128x128 CTA tile, 4 warps (2x2) of 64x64, BK=32,
// cp.async double-buffered. smem rows are 64B data + 16B pad.
// ---------------------------------------------------------------------------
#define ROWB        80
#define TILE_B      (128 * ROWB)          // 10240

// ===== scores: 3-term split (Ah*Bh + Al*Bh + Ah*Bl), mask + *log2e epilogue
#define STAGE3      (4 * TILE_B)          // 40960
#define SMEM3       (2 * STAGE3)          // 81920

__global__ __launch_bounds__(128, 2) void gemm3_scores(
    const __nv_bfloat16* __restrict__ Ah, const __nv_bfloat16* __restrict__ Al,
    const __nv_bfloat16* __restrict__ Bh, const __nv_bfloat16* __restrict__ Bl,
    const int* __restrict__ mask, float* __restrict__ out)
{
    extern __shared__ char smem[];
    const uint32_t sbase = smem_to_u32(smem);
    const int tid  = threadIdx.x;
    const int warp = tid >> 5;
    const int lane = tid & 31;
    const int bm = blockIdx.y * 128;
    const int bn = blockIdx.x * 128;
    const int wm = (warp & 1) * 64;
    const int wn = (warp >> 1) * 64;
    const int lr  = lane >> 2;
    const int lc4 = (lane & 3) * 4;

    float acc[4][8][4];
    #pragma unroll
    for (int mt = 0; mt < 4; mt++)
        #pragma unroll
        for (int nt = 0; nt < 8; nt++)
            #pragma unroll
            for (int r = 0; r < 4; r++) acc[mt][nt][r] = 0.0f;

    #define ISSUE3(cc, buf) do { \
        const int k0_ = (cc) << 5; \
        _Pragma("unroll") \
        for (int p = 0; p < 4; p++) { \
            const int v_   = tid + p * 128; \
            const int row_ = v_ >> 2; \
            const int c16_ = v_ & 3; \
            const uint32_t dst_ = sbase + (buf) * STAGE3 \
                                + row_ * ROWB + c16_ * 16; \
            const size_t ga_ = (size_t)(bm + row_) * DM + k0_ + c16_ * 8; \
            const size_t gb_ = (size_t)(bn + row_) * DM + k0_ + c16_ * 8; \
            CP16(dst_ + 0 * TILE_B, Ah + ga_); \
            CP16(dst_ + 1 * TILE_B, Al + ga_); \
            CP16(dst_ + 2 * TILE_B, Bh + gb_); \
            CP16(dst_ + 3 * TILE_B, Bl + gb_); \
        } \
        CP_COMMIT(); \
    } while (0)

    ISSUE3(0, 0);

    const int NC = DM >> 5;
    for (int c = 0; c < NC; c++) {
        CP_WAIT0();
        __syncthreads();
        if (c + 1 < NC) ISSUE3(c + 1, (c + 1) & 1);

        const uint32_t sA_h = sbase + (c & 1) * STAGE3;
        const uint32_t sA_l = sA_h + TILE_B;
        const uint32_t sB_h = sA_h + 2 * TILE_B;
        const uint32_t sB_l = sA_h + 3 * TILE_B;

        #pragma unroll
        for (int ks = 0; ks < 2; ks++) {
            const uint32_t kb = ks * 32 + lc4;

            uint32_t ah[4][4], al[4][4];
            #pragma unroll
            for (int mt = 0; mt < 4; mt++) {
                const uint32_t r0 = sA_h + (wm + mt * 16 + lr) * ROWB + kb;
                LDS32(ah[mt][0], r0);
                LDS32(ah[mt][1], r0 + 8 * ROWB);
                LDS32(ah[mt][2], r0 + 16);
                LDS32(ah[mt][3], r0 + 8 * ROWB + 16);
                const uint32_t r1 = sA_l + (wm + mt * 16 + lr) * ROWB + kb;
                LDS32(al[mt][0], r1);
                LDS32(al[mt][1], r1 + 8 * ROWB);
                LDS32(al[mt][2], r1 + 16);
                LDS32(al[mt][3], r1 + 8 * ROWB + 16);
            }
            #pragma unroll
            for (int nt = 0; nt < 8; nt++) {
                uint32_t bh[2], bl[2];
                const uint32_t r0 = sB_h + (wn + nt * 8 + lr) * ROWB + kb;
                LDS32(bh[0], r0);
                LDS32(bh[1], r0 + 16);
                const uint32_t r1 = sB_l + (wn + nt * 8 + lr) * ROWB + kb;
                LDS32(bl[0], r1);
                LDS32(bl[1], r1 + 16);
                #pragma unroll
                for (int mt = 0; mt < 4; mt++)
                    mma16816_bf16(acc[mt][nt], ah[mt], bh);
                #pragma unroll
                for (int mt = 0; mt < 4; mt++)
                    mma16816_bf16(acc[mt][nt], al[mt], bh);
                #pragma unroll
                for (int mt = 0; mt < 4; mt++)
                    mma16816_bf16(acc[mt][nt], ah[mt], bl);
            }
        }
        __syncthreads();
    }
    #undef ISSUE3

    // Epilogue: scale by log2e, apply mask -> NEG_SCALED
    #pragma unroll
    for (int mt = 0; mt < 4; mt++) {
        #pragma unroll
        for (int half = 0; half < 2; half++) {
            const size_t rg = (size_t)(bm + wm + mt * 16 + lr + half * 8);
            #pragma unroll
            for (int nt = 0; nt < 8; nt++) {
                const size_t o = rg * (size_t)N_ATOMS
                               + (bn + wn + nt * 8 + (lane & 3) * 2);
                int2 mv = *reinterpret_cast<const int2*>(mask + o);
                float2 v;
                v.x = mv.x ? acc[mt][nt][half * 2 + 0] * LOG2E : NEG_SCALED;
                v.y = mv.y ? acc[mt][nt][half * 2 + 1] * LOG2E : NEG_SCALED;
                *reinterpret_cast<float2*>(out + o) = v;
            }
        }
    }
}

// ===== recon: 1-term fp16 (Wf * DTf), epilogue scales row by inv[row]
#define STAGE1      (2 * TILE_B)          // 20480
#define SMEM1       (2 * STAGE1)          // 40960

__global__ __launch_bounds__(128, 2) void gemm1_recon(
    const __half* __restrict__ A, const __half* __restrict__ B,
    const float* __restrict__ invp, float* __restrict__ out)
{
    extern __shared__ char smem[];
    const uint32_t sbase = smem_to_u32(smem);
    const int tid  = threadIdx.x;
    const int warp = tid >> 5;
    const int lane = tid & 31;
    const int bm = blockIdx.y * 128;
    const int bn = blockIdx.x * 128;
    const int wm = (warp & 1) * 64;
    const int wn = (warp >> 1) * 64;
    const int lr  = lane >> 2;
    const int lc4 = (lane & 3) * 4;

    float acc[4][8][4];
    #pragma unroll
    for (int mt = 0; mt < 4; mt++)
        #pragma unroll
        for (int nt = 0; nt < 8; nt++)
            #pragma unroll
            for (int r = 0; r < 4; r++) acc[mt][nt][r] = 0.0f;

    #define ISSUE1(cc, buf) do { \
        const int k0_ = (cc) << 5; \
        _Pragma("unroll") \
        for (int p = 0; p < 4; p++) { \
            const int v_   = tid + p * 128; \
            const int row_ = v_ >> 2; \
            const int c16_ = v_ & 3; \
            const uint32_t dst_ = sbase + (buf) * STAGE1 \
                                + row_ * ROWB + c16_ * 16; \
            const size_t ga_ = (size_t)(bm + row_) * N_ATOMS + k0_ + c16_ * 8; \
            const size_t gb_ = (size_t)(bn + row_) * N_ATOMS + k0_ + c16_ * 8; \
            CP16(dst_ + 0 * TILE_B, A + ga_); \
            CP16(dst_ + 1 * TILE_B, B + gb_); \
        } \
        CP_COMMIT(); \
    } while (0)

    ISSUE1(0, 0);

    const int NC = N_ATOMS >> 5;
    for (int c = 0; c < NC; c++) {
        CP_WAIT0();
        __syncthreads();
        if (c + 1 < NC) ISSUE1(c + 1, (c + 1) & 1);

        const uint32_t sA = sbase + (c & 1) * STAGE1;
        const uint32_t sB = sA + TILE_B;

        #pragma unroll
        for (int ks = 0; ks < 2; ks++) {
            const uint32_t kb = ks * 32 + lc4;
            uint32_t ah[4][4];
            #pragma unroll
            for (int mt = 0; mt < 4; mt++) {
                const uint32_t r0 = sA + (wm + mt * 16 + lr) * ROWB + kb;
                LDS32(ah[mt][0], r0);
                LDS32(ah[mt][1], r0 + 8 * ROWB);
                LDS32(ah[mt][2], r0 + 16);
                LDS32(ah[mt][3], r0 + 8 * ROWB + 16);
            }
            #pragma unroll
            for (int nt = 0; nt < 8; nt++) {
                uint32_t bh[2];
                const uint32_t r0 = sB + (wn + nt * 8 + lr) * ROWB + kb;
                LDS32(bh[0], r0);
                LDS32(bh[1], r0 + 16);
                #pragma unroll
                for (int mt = 0; mt < 4; mt++)
                    mma16816_f16(acc[mt][nt], ah[mt], bh);
            }
        }
        __syncthreads();
    }
    #undef ISSUE1

    #pragma unroll
    for (int mt = 0; mt < 4; mt++) {
        #pragma unroll
        for (int half = 0; half < 2; half++) {
            const int rloc = bm + wm + mt * 16 + lr + half * 8;
            const float inv = invp[rloc];
            const size_t rg = (size_t)rloc;
            #pragma unroll
            for (int nt = 0; nt < 8; nt++) {
                const size_t o = rg * (size_t)DM
                               + (bn + wn + nt * 8 + (lane & 3) * 2);
                float2 v;
                v.x = acc[mt][nt][half * 2 + 0] * inv;
                v.y = acc[mt][nt][half * 2 + 1] * inv;
                *reinterpret_cast<float2*>(out + o) = v;
            }
        }
    }
}

// ---------------------------------------------------------------------------
// Fused softmax: scores are pre-scaled by log2e. Pass 1: top-2 + max.
// Pass 2: w = 2^(s - max) via ex2.approx, accumulate sum, write fp16
// (unnormalized). inv[row] = 1/sum applied later in recon epilogue.
// ---------------------------------------------------------------------------
__global__ __launch_bounds__(256) void softmax_top2_kernel(
    const float* __restrict__ S, __half* __restrict__ Wf,
    float* __restrict__ invp, int* __restrict__ top2)
{
    const int row = blockIdx.x;
    const float* s = S + (size_t)row * N_ATOMS;
    const int tid = threadIdx.x;

    __shared__ float sv1[256], sv2[256];
    __shared__ int   si1[256], si2[256];

    float v1 = -INFINITY, v2 = -INFINITY;
    int   i1 = 0x7fffffff, i2 = 0x7fffffff;

    #define INSERT(v, i) do { \
        if ((v) > v1 || ((v) == v1 && (i) < i1)) { \
            v2 = v1; i2 = i1; v1 = (v); i1 = (i); \
        } else if ((v) > v2 || ((v) == v2 && (i) < i2)) { \
            v2 = (v); i2 = (i); \
        } \
    } while (0)

    for (int c0 = tid * 4; c0 < N_ATOMS; c0 += 1024) {
        float4 v = *reinterpret_cast<const float4*>(s + c0);
        INSERT(v.x, c0 + 0); INSERT(v.y, c0 + 1);
        INSERT(v.z, c0 + 2); INSERT(v.w, c0 + 3);
    }
    sv1[tid] = v1; si1[tid] = i1; sv2[tid] = v2; si2[tid] = i2;
    __syncthreads();
    for (int off = 128; off > 0; off >>= 1) {
        if (tid < off) {
            v1 = sv1[tid]; i1 = si1[tid]; v2 = sv2[tid]; i2 = si2[tid];
            float ov1 = sv1[tid + off], ov2 = sv2[tid + off];
            int   oi1 = si1[tid + off], oi2 = si2[tid + off];
            INSERT(ov1, oi1); INSERT(ov2, oi2);
            sv1[tid] = v1; si1[tid] = i1; sv2[tid] = v2; si2[tid] = i2;
        }
        __syncthreads();
    }
    #undef INSERT

    const float rmax = sv1[0];
    if (tid == 0) { top2[row * 2] = si1[0]; top2[row * 2 + 1] = si2[0]; }
    __syncthreads();

    // Single exp pass: compute, write fp16, accumulate sum
    __half* wf = Wf + (size_t)row * N_ATOMS;
    float lsum = 0.0f;
    for (int c0 = tid * 4; c0 < N_ATOMS; c0 += 1024) {
        float4 v = *reinterpret_cast<const float4*>(s + c0);
        float w0 = ex2f(v.x - rmax);
        float w1 = ex2f(v.y - rmax);
        float w2 = ex2f(v.z - rmax);
        float w3 = ex2f(v.w - rmax);
        lsum += (w0 + w1) + (w2 + w3);
        ushort4 hv;
        hv.x = __half_as_ushort(__float2half_rn(w0));
        hv.y = __half_as_ushort(__float2half_rn(w1));
        hv.z = __half_as_ushort(__float2half_rn(w2));
        hv.w = __half_as_ushort(__float2half_rn(w3));
        *reinterpret_cast<ushort4*>(wf + c0) = hv;
    }
    sv1[tid] = lsum;
    __syncthreads();
    for (int off = 128; off > 0; off >>= 1) {
        if (tid < off) sv1[tid] += sv1[tid + off];
        __syncthreads();
    }
    if (tid == 0) invp[row] = 1.0f / sv1[0];
}

// ---------------------------------------------------------------------------
// Exact fp32 argmax rescue: recompute the 2 candidate dot products per row.
// ---------------------------------------------------------------------------
__global__ __launch_bounds__(256) void argmax_rescue_kernel(
    const float* __restrict__ X, const float* __restrict__ Dict,
    const int* __restrict__ top2, float* __restrict__ argmax_out)
{
    const int row = blockIdx.x * 8 + (threadIdx.x >> 5);
    const int lid = threadIdx.x & 31;
    const int i1 = top2[row * 2];
    const int i2 = top2[row * 2 + 1];
    const float* x  = X + (size_t)row * DM;
    const float* d1 = Dict + (size_t)i1 * DM;
    const float* d2 = Dict + (size_t)i2 * DM;

    float s1 = 0.0f, s2 = 0.0f;
    for (int k = lid * 4; k < DM; k += 128) {
        float4 xv = *reinterpret_cast<const float4*>(x + k);
        float4 a  = *reinterpret_cast<const float4*>(d1 + k);
        float4 b  = *reinterpret_cast<const float4*>(d2 + k);
        s1 += xv.x * a.x + xv.y * a.y + xv.z * a.z + xv.w * a.w;
        s2 += xv.x * b.x + xv.y * b.y + xv.z * b.z + xv.w * b.w;
    }
    #pragma unroll
    for (int off = 16; off > 0; off >>= 1) {
        s1 += __shfl_xor_sync(0xffffffffu, s1, off);
        s2 += __shfl_xor_sync(0xffffffffu, s2, off);
    }
    if (lid == 0) {
        int best = (s1 > s2 || (s1 == s2 && i1 < i2)) ? i1 : i2;
        argmax_out[row] = (float)best;
    }
}

// ---------------------------------------------------------------------------
// Launch
// ---------------------------------------------------------------------------
extern "C" void kernel_launch(void* const* d_in, const int* in_sizes, int n_in,
                              void* d_out, int out_size)
{
    const float* X    = (const float*)d_in[0];
    const float* Dict = (const float*)d_in[1];
    const int*   mask = (const int*)d_in[2];
    float* out = (float*)d_out;

    float* scores; cudaGetSymbolAddress((void**)&scores, g_scores);
    __nv_bfloat16 *Xh, *Xl, *Dh, *Dl;
    cudaGetSymbolAddress((void**)&Xh, g_Xh);
    cudaGetSymbolAddress((void**)&Xl, g_Xl);
    cudaGetSymbolAddress((void**)&Dh, g_Dh);
    cudaGetSymbolAddress((void**)&Dl, g_Dl);
    __half *DTf, *Wf;
    cudaGetSymbolAddress((void**)&DTf, g_DTf);
    cudaGetSymbolAddress((void**)&Wf, g_Wf);
    float* invp; cudaGetSymbolAddress((void**)&invp, g_inv);
    int* top2; cudaGetSymbolAddress((void**)&top2, g_top2);

    float* recon_out  = out;
    float* argmax_out = out + (size_t)M_ROWS * DM;

    static bool attr_set = false;
    if (!attr_set) {
        cudaFuncSetAttribute(gemm3_scores,
                             cudaFuncAttributeMaxDynamicSharedMemorySize, SMEM3);
        cudaFuncSetAttribute(gemm1_recon,
                             cudaFuncAttributeMaxDynamicSharedMemorySize, SMEM1);
        attr_set = true;
    }

    // 1) hi/lo splits of X and dict (K-major) + transposed dict (fp16)
    {
        int n4x = (M_ROWS * DM) / 4;
        split_hilo_kernel<<<(n4x + 255) / 256, 256>>>(X, Xh, Xl, n4x);
        int n4d = (N_ATOMS * DM) / 4;
        split_hilo_kernel<<<(n4d + 255) / 256, 256>>>(Dict, Dh, Dl, n4d);
        dim3 grid(DM / 32, N_ATOMS / 32), blk(32, 8);
        transpose_f16_kernel<<<grid, blk>>>(Dict, DTf);
    }

    // 2) scores*log2e = (X · dict^T)*log2e with fused mask (3-term split)
    {
        dim3 grid(N_ATOMS / 128, M_ROWS / 128);
        gemm3_scores<<<grid, 128, SMEM3>>>(Xh, Xl, Dh, Dl, mask, scores);
    }

    // 3) fused softmax: top-2, exp via MUFU, unnormalized fp16 weights + inv
    softmax_top2_kernel<<<M_ROWS, 256>>>(scores, Wf, invp, top2);

    // 4) exact fp32 argmax among the two candidates
    argmax_rescue_kernel<<<M_ROWS / 8, 256>>>(X, Dict, top2, argmax_out);

    // 5) reconstruction = (Wf · DTf) * inv[row]  (1-term fp16)
    {
        dim3 grid(DM / 128, M_ROWS / 128);
        gemm1_recon<<<grid, 128, SMEM1>>>(Wf, DTf, invp, recon_out);
    }
}

// round 7
// speedup vs baseline: 5.7729x; 1.4487x over previous
#include <cuda_runtime.h>
#include <cuda_fp16.h>
#include <math.h>
#include <stdint.h>

// ---------------------------------------------------------------------------
// Problem dims
// ---------------------------------------------------------------------------
#define M_ROWS  8192      // 4 * 2048
#define N_ATOMS 16384
#define DM      1024
#define LOG2E   1.4426950408889634f
#define NEG_SCALED (-1.4426950e9f)   // NEG_INF * log2e

// ---------------------------------------------------------------------------
// Scratch (__device__ globals; allocation APIs are forbidden)
// ---------------------------------------------------------------------------
__device__ float   g_scores[(size_t)M_ROWS * N_ATOMS];     // 512 MB
__device__ __half  g_Xf[(size_t)M_ROWS * DM];
__device__ __half  g_Df[(size_t)N_ATOMS * DM];             // dict fp16 K-major
__device__ __half  g_DTf[(size_t)DM * N_ATOMS];            // dict^T fp16
__device__ __half  g_Wf[(size_t)M_ROWS * N_ATOMS];         // 256 MB fp16
__device__ float   g_inv[M_ROWS];
__device__ int     g_top4[M_ROWS * 4];

// ---------------------------------------------------------------------------
// Low-level helpers (sm_80+ baseline PTX only — NO tcgen05 on plain sm_103)
// ---------------------------------------------------------------------------
__device__ __forceinline__ uint32_t smem_to_u32(const void* p) {
    uint32_t a;
    asm("{ .reg .u64 t; cvta.to.shared.u64 t, %1; cvt.u32.u64 %0, t; }"
        : "=r"(a) : "l"(p));
    return a;
}

#define CP16(dst, src) \
    asm volatile("cp.async.cg.shared.global [%0], [%1], 16;" \
                 :: "r"(dst), "l"(src) : "memory")
#define CP_COMMIT() asm volatile("cp.async.commit_group;" ::: "memory")
#define CP_WAIT0()  asm volatile("cp.async.wait_group 0;"  ::: "memory")

#define LDS32(v, a) \
    asm volatile("ld.shared.b32 %0, [%1];" : "=r"(v) : "r"(a))

__device__ __forceinline__ void mma16816_f16(float* c, const uint32_t* a,
                                             const uint32_t* b) {
    asm volatile(
        "mma.sync.aligned.m16n8k16.row.col.f32.f16.f16.f32 "
        "{%0,%1,%2,%3}, {%4,%5,%6,%7}, {%8,%9}, {%0,%1,%2,%3};"
        : "+f"(c[0]), "+f"(c[1]), "+f"(c[2]), "+f"(c[3])
        : "r"(a[0]), "r"(a[1]), "r"(a[2]), "r"(a[3]), "r"(b[0]), "r"(b[1]));
}

__device__ __forceinline__ float ex2f(float x) {
    float y;
    asm("ex2.approx.ftz.f32 %0, %1;" : "=f"(y) : "f"(x));
    return y;
}

// ---------------------------------------------------------------------------
// Conversion kernels
// ---------------------------------------------------------------------------
__global__ __launch_bounds__(256) void to_f16_kernel(
    const float* __restrict__ src, __half* __restrict__ dst, int n4)
{
    int i = blockIdx.x * blockDim.x + threadIdx.x;
    if (i >= n4) return;
    float4 v = reinterpret_cast<const float4*>(src)[i];
    ushort4 hv;
    hv.x = __half_as_ushort(__float2half_rn(v.x));
    hv.y = __half_as_ushort(__float2half_rn(v.y));
    hv.z = __half_as_ushort(__float2half_rn(v.z));
    hv.w = __half_as_ushort(__float2half_rn(v.w));
    reinterpret_cast<ushort4*>(dst)[i] = hv;
}

// dict [N_ATOMS][DM] fp32 -> DTf [DM][N_ATOMS] fp16
__global__ __launch_bounds__(256) void transpose_f16_kernel(
    const float* __restrict__ dict, __half* __restrict__ DTf)
{
    __shared__ float t[32][33];
    const int bx = blockIdx.x;   // DM tile
    const int by = blockIdx.y;   // atom tile
    const int tx = threadIdx.x;  // 0..31
    const int ty = threadIdx.y;  // 0..7
    #pragma unroll
    for (int k = 0; k < 32; k += 8)
        t[ty + k][tx] = dict[(size_t)(by * 32 + ty + k) * DM + bx * 32 + tx];
    __syncthreads();
    #pragma unroll
    for (int k = 0; k < 32; k += 8) {
        size_t o = (size_t)(bx * 32 + ty + k) * N_ATOMS + by * 32 + tx;
        DTf[o] = __float2half_rn(t[tx][ty + k]);
    }
}

// ---------------------------------------------------------------------------
// Unified 1-term fp16 GEMM: out[128x128 tile] = A[M,K] · B[N,K]^T
// MASK=true : epilogue applies mask -> NEG_SCALED, scales by LOG2E (scores)
// MASK=false: epilogue scales row by invp[row] (recon)
// 128 threads = 4 warps (2x2) of 64x64, BK=32, cp.async double-buffered.
// smem rows: 64B data + 16B pad.
// ---------------------------------------------------------------------------
#define ROWB     80
#define TILE_B   (128 * ROWB)          // 10240
#define STAGE    (2 * TILE_B)          // 20480
#define SMEMG    (2 * STAGE)           // 40960

template <bool MASK>
__global__ __launch_bounds__(128, 2) void gemm_f16(
    const __half* __restrict__ A, const __half* __restrict__ B, int Kdim,
    const int* __restrict__ mask, const float* __restrict__ invp,
    float* __restrict__ out, int out_ld)
{
    extern __shared__ char smem[];
    const uint32_t sbase = smem_to_u32(smem);
    const int tid  = threadIdx.x;
    const int warp = tid >> 5;
    const int lane = tid & 31;
    const int bm = blockIdx.y * 128;
    const int bn = blockIdx.x * 128;
    const int wm = (warp & 1) * 64;
    const int wn = (warp >> 1) * 64;
    const int lr  = lane >> 2;
    const int lc4 = (lane & 3) * 4;

    float acc[4][8][4];
    #pragma unroll
    for (int mt = 0; mt < 4; mt++)
        #pragma unroll
        for (int nt = 0; nt < 8; nt++)
            #pragma unroll
            for (int r = 0; r < 4; r++) acc[mt][nt][r] = 0.0f;

    #define ISSUEG(cc, buf) do { \
        const int k0_ = (cc) << 5; \
        _Pragma("unroll") \
        for (int p = 0; p < 4; p++) { \
            const int v_   = tid + p * 128; \
            const int row_ = v_ >> 2; \
            const int c16_ = v_ & 3; \
            const uint32_t dst_ = sbase + (buf) * STAGE \
                                + row_ * ROWB + c16_ * 16; \
            const size_t ga_ = (size_t)(bm + row_) * Kdim + k0_ + c16_ * 8; \
            const size_t gb_ = (size_t)(bn + row_) * Kdim + k0_ + c16_ * 8; \
            CP16(dst_ + 0 * TILE_B, A + ga_); \
            CP16(dst_ + 1 * TILE_B, B + gb_); \
        } \
        CP_COMMIT(); \
    } while (0)

    ISSUEG(0, 0);

    const int NC = Kdim >> 5;
    for (int c = 0; c < NC; c++) {
        CP_WAIT0();
        __syncthreads();
        if (c + 1 < NC) ISSUEG(c + 1, (c + 1) & 1);

        const uint32_t sA = sbase + (c & 1) * STAGE;
        const uint32_t sB = sA + TILE_B;

        #pragma unroll
        for (int ks = 0; ks < 2; ks++) {
            const uint32_t kb = ks * 32 + lc4;
            uint32_t ah[4][4];
            #pragma unroll
            for (int mt = 0; mt < 4; mt++) {
                const uint32_t r0 = sA + (wm + mt * 16 + lr) * ROWB + kb;
                LDS32(ah[mt][0], r0);
                LDS32(ah[mt][1], r0 + 8 * ROWB);
                LDS32(ah[mt][2], r0 + 16);
                LDS32(ah[mt][3], r0 + 8 * ROWB + 16);
            }
            #pragma unroll
            for (int nt = 0; nt < 8; nt++) {
                uint32_t bh[2];
                const uint32_t r0 = sB + (wn + nt * 8 + lr) * ROWB + kb;
                LDS32(bh[0], r0);
                LDS32(bh[1], r0 + 16);
                #pragma unroll
                for (int mt = 0; mt < 4; mt++)
                    mma16816_f16(acc[mt][nt], ah[mt], bh);
            }
        }
        __syncthreads();
    }
    #undef ISSUEG

    // Epilogue
    #pragma unroll
    for (int mt = 0; mt < 4; mt++) {
        #pragma unroll
        for (int half = 0; half < 2; half++) {
            const int rloc = bm + wm + mt * 16 + lr + half * 8;
            float inv = 1.0f;
            if (!MASK) inv = invp[rloc];
            const size_t rg = (size_t)rloc;
            #pragma unroll
            for (int nt = 0; nt < 8; nt++) {
                const size_t o = rg * (size_t)out_ld
                               + (bn + wn + nt * 8 + (lane & 3) * 2);
                float2 v;
                if (MASK) {
                    int2 mv = *reinterpret_cast<const int2*>(mask + o);
                    v.x = mv.x ? acc[mt][nt][half * 2 + 0] * LOG2E : NEG_SCALED;
                    v.y = mv.y ? acc[mt][nt][half * 2 + 1] * LOG2E : NEG_SCALED;
                } else {
                    v.x = acc[mt][nt][half * 2 + 0] * inv;
                    v.y = acc[mt][nt][half * 2 + 1] * inv;
                }
                *reinterpret_cast<float2*>(out + o) = v;
            }
        }
    }
}

// ---------------------------------------------------------------------------
// Fused softmax: scores are pre-scaled by log2e. Pass 1: top-4 + max.
// Pass 2: w = 2^(s - max) via ex2.approx, accumulate sum, write fp16
// (unnormalized). inv[row] = 1/sum applied later in recon epilogue.
// ---------------------------------------------------------------------------
#define BETTER(v, i, V, I) ((v) > (V) || ((v) == (V) && (i) < (I)))

__global__ __launch_bounds__(256) void softmax_top4_kernel(
    const float* __restrict__ S, __half* __restrict__ Wf,
    float* __restrict__ invp, int* __restrict__ top4)
{
    const int row = blockIdx.x;
    const float* s = S + (size_t)row * N_ATOMS;
    const int tid = threadIdx.x;

    __shared__ float sv[4][256];
    __shared__ int   si[4][256];

    float tv[4] = {-INFINITY, -INFINITY, -INFINITY, -INFINITY};
    int   ti[4] = {0x7fffffff, 0x7fffffff, 0x7fffffff, 0x7fffffff};

    #define INS4(v, i) do { \
        float v_ = (v); int i_ = (i); \
        if (BETTER(v_, i_, tv[3], ti[3])) { \
            tv[3] = v_; ti[3] = i_; \
            if (BETTER(tv[3], ti[3], tv[2], ti[2])) { \
                float tv_ = tv[2]; int ti_ = ti[2]; \
                tv[2] = tv[3]; ti[2] = ti[3]; tv[3] = tv_; ti[3] = ti_; \
                if (BETTER(tv[2], ti[2], tv[1], ti[1])) { \
                    tv_ = tv[1]; ti_ = ti[1]; \
                    tv[1] = tv[2]; ti[1] = ti[2]; tv[2] = tv_; ti[2] = ti_; \
                    if (BETTER(tv[1], ti[1], tv[0], ti[0])) { \
                        tv_ = tv[0]; ti_ = ti[0]; \
                        tv[0] = tv[1]; ti[0] = ti[1]; tv[1] = tv_; ti[1] = ti_; \
                    } \
                } \
            } \
        } \
    } while (0)

    for (int c0 = tid * 4; c0 < N_ATOMS; c0 += 1024) {
        float4 v = *reinterpret_cast<const float4*>(s + c0);
        INS4(v.x, c0 + 0); INS4(v.y, c0 + 1);
        INS4(v.z, c0 + 2); INS4(v.w, c0 + 3);
    }
    #pragma unroll
    for (int j = 0; j < 4; j++) { sv[j][tid] = tv[j]; si[j][tid] = ti[j]; }
    __syncthreads();
    for (int off = 128; off > 0; off >>= 1) {
        if (tid < off) {
            #pragma unroll
            for (int j = 0; j < 4; j++) { tv[j] = sv[j][tid]; ti[j] = si[j][tid]; }
            #pragma unroll
            for (int j = 0; j < 4; j++)
                INS4(sv[j][tid + off], si[j][tid + off]);
            #pragma unroll
            for (int j = 0; j < 4; j++) { sv[j][tid] = tv[j]; si[j][tid] = ti[j]; }
        }
        __syncthreads();
    }
    #undef INS4

    const float rmax = sv[0][0];
    if (tid < 4) top4[row * 4 + tid] = si[tid][0];
    __syncthreads();

    // Single exp pass: compute, write fp16, accumulate sum
    __half* wf = Wf + (size_t)row * N_ATOMS;
    float lsum = 0.0f;
    for (int c0 = tid * 4; c0 < N_ATOMS; c0 += 1024) {
        float4 v = *reinterpret_cast<const float4*>(s + c0);
        float w0 = ex2f(v.x - rmax);
        float w1 = ex2f(v.y - rmax);
        float w2 = ex2f(v.z - rmax);
        float w3 = ex2f(v.w - rmax);
        lsum += (w0 + w1) + (w2 + w3);
        ushort4 hv;
        hv.x = __half_as_ushort(__float2half_rn(w0));
        hv.y = __half_as_ushort(__float2half_rn(w1));
        hv.z = __half_as_ushort(__float2half_rn(w2));
        hv.w = __half_as_ushort(__float2half_rn(w3));
        *reinterpret_cast<ushort4*>(wf + c0) = hv;
    }
    sv[0][tid] = lsum;
    __syncthreads();
    for (int off = 128; off > 0; off >>= 1) {
        if (tid < off) sv[0][tid] += sv[0][tid + off];
        __syncthreads();
    }
    if (tid == 0) invp[row] = 1.0f / sv[0][0];
}

// ---------------------------------------------------------------------------
// Exact fp32 argmax rescue over 4 candidates. One warp per row.
// ---------------------------------------------------------------------------
__global__ __launch_bounds__(256) void argmax_rescue4_kernel(
    const float* __restrict__ X, const float* __restrict__ Dict,
    const int* __restrict__ mask, const int* __restrict__ top4,
    float* __restrict__ argmax_out)
{
    const int row = blockIdx.x * 8 + (threadIdx.x >> 5);
    const int lid = threadIdx.x & 31;
    int ci[4];
    #pragma unroll
    for (int j = 0; j < 4; j++) ci[j] = top4[row * 4 + j];

    const float* x = X + (size_t)row * DM;
    float sc[4] = {0.0f, 0.0f, 0.0f, 0.0f};
    for (int k = lid * 4; k < DM; k += 128) {
        float4 xv = *reinterpret_cast<const float4*>(x + k);
        #pragma unroll
        for (int j = 0; j < 4; j++) {
            float4 d = *reinterpret_cast<const float4*>(
                Dict + (size_t)ci[j] * DM + k);
            sc[j] += xv.x * d.x + xv.y * d.y + xv.z * d.z + xv.w * d.w;
        }
    }
    #pragma unroll
    for (int off = 16; off > 0; off >>= 1)
        #pragma unroll
        for (int j = 0; j < 4; j++)
            sc[j] += __shfl_xor_sync(0xffffffffu, sc[j], off);

    if (lid == 0) {
        const int* mrow = mask + (size_t)row * N_ATOMS;
        float bv = -INFINITY; int bi = 0x7fffffff;
        #pragma unroll
        for (int j = 0; j < 4; j++) {
            float v = mrow[ci[j]] ? sc[j] : -1e9f;
            if (BETTER(v, ci[j], bv, bi)) { bv = v; bi = ci[j]; }
        }
        argmax_out[row] = (float)bi;
    }
}

// ---------------------------------------------------------------------------
// Launch
// ---------------------------------------------------------------------------
extern "C" void kernel_launch(void* const* d_in, const int* in_sizes, int n_in,
                              void* d_out, int out_size)
{
    const float* X    = (const float*)d_in[0];
    const float* Dict = (const float*)d_in[1];
    const int*   mask = (const int*)d_in[2];
    float* out = (float*)d_out;

    float* scores; cudaGetSymbolAddress((void**)&scores, g_scores);
    __half *Xf, *Df, *DTf, *Wf;
    cudaGetSymbolAddress((void**)&Xf, g_Xf);
    cudaGetSymbolAddress((void**)&Df, g_Df);
    cudaGetSymbolAddress((void**)&DTf, g_DTf);
    cudaGetSymbolAddress((void**)&Wf, g_Wf);
    float* invp; cudaGetSymbolAddress((void**)&invp, g_inv);
    int* top4; cudaGetSymbolAddress((void**)&top4, g_top4);

    float* recon_out  = out;
    float* argmax_out = out + (size_t)M_ROWS * DM;

    static bool attr_set = false;
    if (!attr_set) {
        cudaFuncSetAttribute(gemm_f16<true>,
                             cudaFuncAttributeMaxDynamicSharedMemorySize, SMEMG);
        cudaFuncSetAttribute(gemm_f16<false>,
                             cudaFuncAttributeMaxDynamicSharedMemorySize, SMEMG);
        attr_set = true;
    }

    // 1) fp16 conversions: X, dict (K-major), dict^T
    {
        int n4x = (M_ROWS * DM) / 4;
        to_f16_kernel<<<(n4x + 255) / 256, 256>>>(X, Xf, n4x);
        int n4d = (N_ATOMS * DM) / 4;
        to_f16_kernel<<<(n4d + 255) / 256, 256>>>(Dict, Df, n4d);
        dim3 grid(DM / 32, N_ATOMS / 32), blk(32, 8);
        transpose_f16_kernel<<<grid, blk>>>(Dict, DTf);
    }

    // 2) scores*log2e = (Xf · Df^T)*log2e with fused mask (1-term fp16)
    {
        dim3 grid(N_ATOMS / 128, M_ROWS / 128);
        gemm_f16<true><<<grid, 128, SMEMG>>>(
            Xf, Df, DM, mask, nullptr, scores, N_ATOMS);
    }

    // 3) fused softmax: top-4, exp via MUFU, unnormalized fp16 weights + inv
    softmax_top4_kernel<<<M_ROWS, 256>>>(scores, Wf, invp, top4);

    // 4) exact fp32 argmax among the four candidates
    argmax_rescue4_kernel<<<M_ROWS / 8, 256>>>(X, Dict, mask, top4, argmax_out);

    // 5) reconstruction = (Wf · DTf) * inv[row]  (1-term fp16)
    {
        dim3 grid(DM / 128, M_ROWS / 128);
        gemm_f16<false><<<grid, 128, SMEMG>>>(
            Wf, DTf, N_ATOMS, nullptr, invp, recon_out, DM);
    }
}

// round 8
// speedup vs baseline: 6.7159x; 1.1634x over previous
#include <cuda_runtime.h>
#include <cuda_fp16.h>
#include <math.h>
#include <stdint.h>

// ---------------------------------------------------------------------------
// Problem dims
// ---------------------------------------------------------------------------
#define M_ROWS  8192      // 4 * 2048
#define N_ATOMS 16384
#define DM      1024
#define LOG2E   1.4426950408889634f
#define NEG_H   (-60000.0f)   // masked score in fp16 domain (log2-scaled)

// ---------------------------------------------------------------------------
// Scratch (__device__ globals; allocation APIs are forbidden)
// ---------------------------------------------------------------------------
__device__ __half  g_scores[(size_t)M_ROWS * N_ATOMS];     // 256 MB fp16
__device__ __half  g_Xf[(size_t)M_ROWS * DM];
__device__ __half  g_Df[(size_t)N_ATOMS * DM];             // dict fp16 K-major
__device__ __half  g_DTf[(size_t)DM * N_ATOMS];            // dict^T fp16
__device__ __half  g_Wf[(size_t)M_ROWS * N_ATOMS];         // 256 MB fp16
__device__ float   g_inv[M_ROWS];
__device__ int     g_top4[M_ROWS * 4];

// ---------------------------------------------------------------------------
// Low-level helpers (sm_80+ baseline PTX only — NO tcgen05 on plain sm_103)
// ---------------------------------------------------------------------------
__device__ __forceinline__ uint32_t smem_to_u32(const void* p) {
    uint32_t a;
    asm("{ .reg .u64 t; cvta.to.shared.u64 t, %1; cvt.u32.u64 %0, t; }"
        : "=r"(a) : "l"(p));
    return a;
}

#define CP16(dst, src) \
    asm volatile("cp.async.cg.shared.global [%0], [%1], 16;" \
                 :: "r"(dst), "l"(src) : "memory")
#define CP_COMMIT() asm volatile("cp.async.commit_group;" ::: "memory")
#define CP_WAIT0()  asm volatile("cp.async.wait_group 0;"  ::: "memory")

#define LDSM4(r0, r1, r2, r3, addr) \
    asm volatile("ldmatrix.sync.aligned.m8n8.x4.shared.b16 {%0,%1,%2,%3}, [%4];" \
        : "=r"(r0), "=r"(r1), "=r"(r2), "=r"(r3) : "r"(addr))

__device__ __forceinline__ void mma16816_f16(float* c, const uint32_t* a,
                                             const uint32_t* b) {
    asm volatile(
        "mma.sync.aligned.m16n8k16.row.col.f32.f16.f16.f32 "
        "{%0,%1,%2,%3}, {%4,%5,%6,%7}, {%8,%9}, {%0,%1,%2,%3};"
        : "+f"(c[0]), "+f"(c[1]), "+f"(c[2]), "+f"(c[3])
        : "r"(a[0]), "r"(a[1]), "r"(a[2]), "r"(a[3]), "r"(b[0]), "r"(b[1]));
}

__device__ __forceinline__ float ex2f(float x) {
    float y;
    asm("ex2.approx.ftz.f32 %0, %1;" : "=f"(y) : "f"(x));
    return y;
}

// ---------------------------------------------------------------------------
// Conversion kernels
// ---------------------------------------------------------------------------
__global__ __launch_bounds__(256) void to_f16_kernel(
    const float* __restrict__ src, __half* __restrict__ dst, int n4)
{
    int i = blockIdx.x * blockDim.x + threadIdx.x;
    if (i >= n4) return;
    float4 v = reinterpret_cast<const float4*>(src)[i];
    ushort4 hv;
    hv.x = __half_as_ushort(__float2half_rn(v.x));
    hv.y = __half_as_ushort(__float2half_rn(v.y));
    hv.z = __half_as_ushort(__float2half_rn(v.z));
    hv.w = __half_as_ushort(__float2half_rn(v.w));
    reinterpret_cast<ushort4*>(dst)[i] = hv;
}

// dict [N_ATOMS][DM] fp32 -> DTf [DM][N_ATOMS] fp16
__global__ __launch_bounds__(256) void transpose_f16_kernel(
    const float* __restrict__ dict, __half* __restrict__ DTf)
{
    __shared__ float t[32][33];
    const int bx = blockIdx.x;
    const int by = blockIdx.y;
    const int tx = threadIdx.x;
    const int ty = threadIdx.y;
    #pragma unroll
    for (int k = 0; k < 32; k += 8)
        t[ty + k][tx] = dict[(size_t)(by * 32 + ty + k) * DM + bx * 32 + tx];
    __syncthreads();
    #pragma unroll
    for (int k = 0; k < 32; k += 8) {
        size_t o = (size_t)(bx * 32 + ty + k) * N_ATOMS + by * 32 + tx;
        DTf[o] = __float2half_rn(t[tx][ty + k]);
    }
}

// ---------------------------------------------------------------------------
// Unified 1-term fp16 GEMM via ldmatrix + mma.sync.
// out tile 128x128 = A[M,K] · B[N,K]^T
// MASK=true : out is __half, masked -> NEG_H, scaled by LOG2E (scores)
// MASK=false: out is float, row scaled by invp[row] (recon)
// 128 threads = 4 warps (2x2) of 64x64, BK=32, cp.async double-buffered.
// smem rows: 64B data + 16B pad (80B) — conflict-free LDSM phases.
// ---------------------------------------------------------------------------
#define ROWB     80
#define TILE_B   (128 * ROWB)          // 10240
#define STAGE    (2 * TILE_B)          // 20480
#define SMEMG    (2 * STAGE)           // 40960

template <bool MASK>
__global__ __launch_bounds__(128, 2) void gemm_f16(
    const __half* __restrict__ A, const __half* __restrict__ B, int Kdim,
    const int* __restrict__ mask, const float* __restrict__ invp,
    void* __restrict__ outp, int out_ld)
{
    extern __shared__ char smem[];
    const uint32_t sbase = smem_to_u32(smem);
    const int tid  = threadIdx.x;
    const int warp = tid >> 5;
    const int lane = tid & 31;
    const int bm = blockIdx.y * 128;
    const int bn = blockIdx.x * 128;
    const int wm = (warp & 1) * 64;
    const int wn = (warp >> 1) * 64;

    // ldmatrix per-thread address components
    const int a_row = wm + (lane & 15);          // row within A tile
    const int a_kh  = (lane >> 4) * 16;          // k-half byte offset
    const int b_row = wn + ((lane >> 4) << 3) + (lane & 7);
    const int b_kh  = ((lane >> 3) & 1) * 16;

    float acc[4][8][4];
    #pragma unroll
    for (int mt = 0; mt < 4; mt++)
        #pragma unroll
        for (int nt = 0; nt < 8; nt++)
            #pragma unroll
            for (int r = 0; r < 4; r++) acc[mt][nt][r] = 0.0f;

    #define ISSUEG(cc, buf) do { \
        const int k0_ = (cc) << 5; \
        _Pragma("unroll") \
        for (int p = 0; p < 4; p++) { \
            const int v_   = tid + p * 128; \
            const int row_ = v_ >> 2; \
            const int c16_ = v_ & 3; \
            const uint32_t dst_ = sbase + (buf) * STAGE \
                                + row_ * ROWB + c16_ * 16; \
            const size_t ga_ = (size_t)(bm + row_) * Kdim + k0_ + c16_ * 8; \
            const size_t gb_ = (size_t)(bn + row_) * Kdim + k0_ + c16_ * 8; \
            CP16(dst_ + 0 * TILE_B, A + ga_); \
            CP16(dst_ + 1 * TILE_B, B + gb_); \
        } \
        CP_COMMIT(); \
    } while (0)

    ISSUEG(0, 0);

    const int NC = Kdim >> 5;
    for (int c = 0; c < NC; c++) {
        CP_WAIT0();
        __syncthreads();
        if (c + 1 < NC) ISSUEG(c + 1, (c + 1) & 1);

        const uint32_t sA = sbase + (c & 1) * STAGE;
        const uint32_t sB = sA + TILE_B;

        #pragma unroll
        for (int ks = 0; ks < 2; ks++) {
            const uint32_t kb0 = ks * 32;

            uint32_t a[4][4], b[8][2];
            #pragma unroll
            for (int mt = 0; mt < 4; mt++) {
                const uint32_t ad = sA + (a_row + mt * 16) * ROWB + a_kh + kb0;
                LDSM4(a[mt][0], a[mt][1], a[mt][2], a[mt][3], ad);
            }
            #pragma unroll
            for (int p = 0; p < 4; p++) {
                const uint32_t bd = sB + (b_row + p * 16) * ROWB + b_kh + kb0;
                LDSM4(b[2 * p][0], b[2 * p][1], b[2 * p + 1][0], b[2 * p + 1][1], bd);
            }
            #pragma unroll
            for (int nt = 0; nt < 8; nt++)
                #pragma unroll
                for (int mt = 0; mt < 4; mt++)
                    mma16816_f16(acc[mt][nt], a[mt], b[nt]);
        }
        __syncthreads();
    }
    #undef ISSUEG

    // Epilogue
    const int lr = lane >> 2;
    #pragma unroll
    for (int mt = 0; mt < 4; mt++) {
        #pragma unroll
        for (int half = 0; half < 2; half++) {
            const int rloc = bm + wm + mt * 16 + lr + half * 8;
            float inv = 1.0f;
            if (!MASK) inv = invp[rloc];
            const size_t rg = (size_t)rloc;
            #pragma unroll
            for (int nt = 0; nt < 8; nt++) {
                const size_t o = rg * (size_t)out_ld
                               + (bn + wn + nt * 8 + (lane & 3) * 2);
                if (MASK) {
                    int2 mv = *reinterpret_cast<const int2*>(mask + o);
                    float2 v;
                    v.x = mv.x ? acc[mt][nt][half * 2 + 0] * LOG2E : NEG_H;
                    v.y = mv.y ? acc[mt][nt][half * 2 + 1] * LOG2E : NEG_H;
                    *reinterpret_cast<__half2*>((__half*)outp + o) =
                        __float22half2_rn(v);
                } else {
                    float2 v;
                    v.x = acc[mt][nt][half * 2 + 0] * inv;
                    v.y = acc[mt][nt][half * 2 + 1] * inv;
                    *reinterpret_cast<float2*>((float*)outp + o) = v;
                }
            }
        }
    }
}

// ---------------------------------------------------------------------------
// Fused softmax over fp16 log2-scaled scores. Pass 1: top-4 + max.
// Pass 2: w = 2^(s - max), accumulate sum, write fp16 unnormalized weights.
// inv[row] = 1/sum applied in recon epilogue.
// ---------------------------------------------------------------------------
#define BETTER(v, i, V, I) ((v) > (V) || ((v) == (V) && (i) < (I)))

__global__ __launch_bounds__(256) void softmax_top4_kernel(
    const __half* __restrict__ S, __half* __restrict__ Wf,
    float* __restrict__ invp, int* __restrict__ top4)
{
    const int row = blockIdx.x;
    const __half* s = S + (size_t)row * N_ATOMS;
    const int tid = threadIdx.x;

    __shared__ float sv[4][256];
    __shared__ int   si[4][256];

    float tv[4] = {-INFINITY, -INFINITY, -INFINITY, -INFINITY};
    int   ti[4] = {0x7fffffff, 0x7fffffff, 0x7fffffff, 0x7fffffff};

    #define INS4(v, i) do { \
        float v_ = (v); int i_ = (i); \
        if (BETTER(v_, i_, tv[3], ti[3])) { \
            tv[3] = v_; ti[3] = i_; \
            if (BETTER(tv[3], ti[3], tv[2], ti[2])) { \
                float tv_ = tv[2]; int ti_ = ti[2]; \
                tv[2] = tv[3]; ti[2] = ti[3]; tv[3] = tv_; ti[3] = ti_; \
                if (BETTER(tv[2], ti[2], tv[1], ti[1])) { \
                    tv_ = tv[1]; ti_ = ti[1]; \
                    tv[1] = tv[2]; ti[1] = ti[2]; tv[2] = tv_; ti[2] = ti_; \
                    if (BETTER(tv[1], ti[1], tv[0], ti[0])) { \
                        tv_ = tv[0]; ti_ = ti[0]; \
                        tv[0] = tv[1]; ti[0] = ti[1]; tv[1] = tv_; ti[1] = ti_; \
                    } \
                } \
            } \
        } \
    } while (0)

    for (int c0 = tid * 8; c0 < N_ATOMS; c0 += 2048) {
        uint4 u = *reinterpret_cast<const uint4*>(s + c0);
        float2 f0 = __half22float2(*reinterpret_cast<__half2*>(&u.x));
        float2 f1 = __half22float2(*reinterpret_cast<__half2*>(&u.y));
        float2 f2 = __half22float2(*reinterpret_cast<__half2*>(&u.z));
        float2 f3 = __half22float2(*reinterpret_cast<__half2*>(&u.w));
        INS4(f0.x, c0 + 0); INS4(f0.y, c0 + 1);
        INS4(f1.x, c0 + 2); INS4(f1.y, c0 + 3);
        INS4(f2.x, c0 + 4); INS4(f2.y, c0 + 5);
        INS4(f3.x, c0 + 6); INS4(f3.y, c0 + 7);
    }
    #pragma unroll
    for (int j = 0; j < 4; j++) { sv[j][tid] = tv[j]; si[j][tid] = ti[j]; }
    __syncthreads();
    for (int off = 128; off > 0; off >>= 1) {
        if (tid < off) {
            #pragma unroll
            for (int j = 0; j < 4; j++) { tv[j] = sv[j][tid]; ti[j] = si[j][tid]; }
            #pragma unroll
            for (int j = 0; j < 4; j++)
                INS4(sv[j][tid + off], si[j][tid + off]);
            #pragma unroll
            for (int j = 0; j < 4; j++) { sv[j][tid] = tv[j]; si[j][tid] = ti[j]; }
        }
        __syncthreads();
    }
    #undef INS4

    const float rmax = sv[0][0];
    if (tid < 4) top4[row * 4 + tid] = si[tid][0];
    __syncthreads();

    // Exp pass: compute, write fp16 weights, accumulate sum
    __half* wf = Wf + (size_t)row * N_ATOMS;
    float lsum = 0.0f;
    for (int c0 = tid * 8; c0 < N_ATOMS; c0 += 2048) {
        uint4 u = *reinterpret_cast<const uint4*>(s + c0);
        float2 f0 = __half22float2(*reinterpret_cast<__half2*>(&u.x));
        float2 f1 = __half22float2(*reinterpret_cast<__half2*>(&u.y));
        float2 f2 = __half22float2(*reinterpret_cast<__half2*>(&u.z));
        float2 f3 = __half22float2(*reinterpret_cast<__half2*>(&u.w));
        float w0 = ex2f(f0.x - rmax), w1 = ex2f(f0.y - rmax);
        float w2 = ex2f(f1.x - rmax), w3 = ex2f(f1.y - rmax);
        float w4 = ex2f(f2.x - rmax), w5 = ex2f(f2.y - rmax);
        float w6 = ex2f(f3.x - rmax), w7 = ex2f(f3.y - rmax);
        lsum += ((w0 + w1) + (w2 + w3)) + ((w4 + w5) + (w6 + w7));
        uint4 o;
        *reinterpret_cast<__half2*>(&o.x) = __float22half2_rn(make_float2(w0, w1));
        *reinterpret_cast<__half2*>(&o.y) = __float22half2_rn(make_float2(w2, w3));
        *reinterpret_cast<__half2*>(&o.z) = __float22half2_rn(make_float2(w4, w5));
        *reinterpret_cast<__half2*>(&o.w) = __float22half2_rn(make_float2(w6, w7));
        *reinterpret_cast<uint4*>(wf + c0) = o;
    }
    sv[0][tid] = lsum;
    __syncthreads();
    for (int off = 128; off > 0; off >>= 1) {
        if (tid < off) sv[0][tid] += sv[0][tid + off];
        __syncthreads();
    }
    if (tid == 0) invp[row] = 1.0f / sv[0][0];
}

// ---------------------------------------------------------------------------
// Exact fp32 argmax rescue over 4 candidates. One warp per row.
// ---------------------------------------------------------------------------
__global__ __launch_bounds__(256) void argmax_rescue4_kernel(
    const float* __restrict__ X, const float* __restrict__ Dict,
    const int* __restrict__ mask, const int* __restrict__ top4,
    float* __restrict__ argmax_out)
{
    const int row = blockIdx.x * 8 + (threadIdx.x >> 5);
    const int lid = threadIdx.x & 31;
    int ci[4];
    #pragma unroll
    for (int j = 0; j < 4; j++) ci[j] = top4[row * 4 + j];

    const float* x = X + (size_t)row * DM;
    float sc[4] = {0.0f, 0.0f, 0.0f, 0.0f};
    for (int k = lid * 4; k < DM; k += 128) {
        float4 xv = *reinterpret_cast<const float4*>(x + k);
        #pragma unroll
        for (int j = 0; j < 4; j++) {
            float4 d = *reinterpret_cast<const float4*>(
                Dict + (size_t)ci[j] * DM + k);
            sc[j] += xv.x * d.x + xv.y * d.y + xv.z * d.z + xv.w * d.w;
        }
    }
    #pragma unroll
    for (int off = 16; off > 0; off >>= 1)
        #pragma unroll
        for (int j = 0; j < 4; j++)
            sc[j] += __shfl_xor_sync(0xffffffffu, sc[j], off);

    if (lid == 0) {
        const int* mrow = mask + (size_t)row * N_ATOMS;
        float bv = -INFINITY; int bi = 0x7fffffff;
        #pragma unroll
        for (int j = 0; j < 4; j++) {
            float v = mrow[ci[j]] ? sc[j] : -1e9f;
            if (BETTER(v, ci[j], bv, bi)) { bv = v; bi = ci[j]; }
        }
        argmax_out[row] = (float)bi;
    }
}

// ---------------------------------------------------------------------------
// Launch
// ---------------------------------------------------------------------------
extern "C" void kernel_launch(void* const* d_in, const int* in_sizes, int n_in,
                              void* d_out, int out_size)
{
    const float* X    = (const float*)d_in[0];
    const float* Dict = (const float*)d_in[1];
    const int*   mask = (const int*)d_in[2];
    float* out = (float*)d_out;

    __half *scores, *Xf, *Df, *DTf, *Wf;
    cudaGetSymbolAddress((void**)&scores, g_scores);
    cudaGetSymbolAddress((void**)&Xf, g_Xf);
    cudaGetSymbolAddress((void**)&Df, g_Df);
    cudaGetSymbolAddress((void**)&DTf, g_DTf);
    cudaGetSymbolAddress((void**)&Wf, g_Wf);
    float* invp; cudaGetSymbolAddress((void**)&invp, g_inv);
    int* top4; cudaGetSymbolAddress((void**)&top4, g_top4);

    float* recon_out  = out;
    float* argmax_out = out + (size_t)M_ROWS * DM;

    static bool attr_set = false;
    if (!attr_set) {
        cudaFuncSetAttribute(gemm_f16<true>,
                             cudaFuncAttributeMaxDynamicSharedMemorySize, SMEMG);
        cudaFuncSetAttribute(gemm_f16<false>,
                             cudaFuncAttributeMaxDynamicSharedMemorySize, SMEMG);
        attr_set = true;
    }

    // 1) fp16 conversions: X, dict (K-major), dict^T
    {
        int n4x = (M_ROWS * DM) / 4;
        to_f16_kernel<<<(n4x + 255) / 256, 256>>>(X, Xf, n4x);
        int n4d = (N_ATOMS * DM) / 4;
        to_f16_kernel<<<(n4d + 255) / 256, 256>>>(Dict, Df, n4d);
        dim3 grid(DM / 32, N_ATOMS / 32), blk(32, 8);
        transpose_f16_kernel<<<grid, blk>>>(Dict, DTf);
    }

    // 2) scores*log2e (fp16) = (Xf · Df^T)*log2e with fused mask
    {
        dim3 grid(N_ATOMS / 128, M_ROWS / 128);
        gemm_f16<true><<<grid, 128, SMEMG>>>(
            Xf, Df, DM, mask, nullptr, scores, N_ATOMS);
    }

    // 3) fused softmax: top-4, exp via MUFU, unnormalized fp16 weights + inv
    softmax_top4_kernel<<<M_ROWS, 256>>>(scores, Wf, invp, top4);

    // 4) exact fp32 argmax among the four candidates
    argmax_rescue4_kernel<<<M_ROWS / 8, 256>>>(X, Dict, mask, top4, argmax_out);

    // 5) reconstruction = (Wf · DTf) * inv[row]
    {
        dim3 grid(DM / 128, M_ROWS / 128);
        gemm_f16<false><<<grid, 128, SMEMG>>>(
            Wf, DTf, N_ATOMS, nullptr, invp, recon_out, DM);
    }
}

// round 9
// speedup vs baseline: 7.0887x; 1.0555x over previous
#include <cuda_runtime.h>
#include <cuda_fp16.h>
#include <math.h>
#include <stdint.h>

// ---------------------------------------------------------------------------
// Problem dims
// ---------------------------------------------------------------------------
#define M_ROWS  8192      // 4 * 2048
#define N_ATOMS 16384
#define DM      1024
#define LOG2E   1.4426950408889634f
#define NEG_H   (-60000.0f)   // masked score in fp16 domain (log2-scaled)

// ---------------------------------------------------------------------------
// Scratch (__device__ globals; allocation APIs are forbidden)
// ---------------------------------------------------------------------------
__device__ __half  g_scores[(size_t)M_ROWS * N_ATOMS];     // 256 MB fp16
__device__ __half  g_Xf[(size_t)M_ROWS * DM];
__device__ __half  g_Df[(size_t)N_ATOMS * DM];             // dict fp16 K-major
__device__ __half  g_DTf[(size_t)DM * N_ATOMS];            // dict^T fp16
__device__ __half  g_Wf[(size_t)M_ROWS * N_ATOMS];         // 256 MB fp16
__device__ float   g_inv[M_ROWS];
__device__ int     g_top4[M_ROWS * 4];

// ---------------------------------------------------------------------------
// Low-level helpers (sm_80+ baseline PTX only — NO tcgen05 on plain sm_103)
// ---------------------------------------------------------------------------
__device__ __forceinline__ uint32_t smem_to_u32(const void* p) {
    uint32_t a;
    asm("{ .reg .u64 t; cvta.to.shared.u64 t, %1; cvt.u32.u64 %0, t; }"
        : "=r"(a) : "l"(p));
    return a;
}

#define CP16(dst, src) \
    asm volatile("cp.async.cg.shared.global [%0], [%1], 16;" \
                 :: "r"(dst), "l"(src) : "memory")
#define CP_COMMIT() asm volatile("cp.async.commit_group;" ::: "memory")
#define CP_WAIT2()  asm volatile("cp.async.wait_group 2;"  ::: "memory")

#define LDSM4(r0, r1, r2, r3, addr) \
    asm volatile("ldmatrix.sync.aligned.m8n8.x4.shared.b16 {%0,%1,%2,%3}, [%4];" \
        : "=r"(r0), "=r"(r1), "=r"(r2), "=r"(r3) : "r"(addr))

__device__ __forceinline__ void mma16816_f16(float* c, const uint32_t* a,
                                             const uint32_t* b) {
    asm volatile(
        "mma.sync.aligned.m16n8k16.row.col.f32.f16.f16.f32 "
        "{%0,%1,%2,%3}, {%4,%5,%6,%7}, {%8,%9}, {%0,%1,%2,%3};"
        : "+f"(c[0]), "+f"(c[1]), "+f"(c[2]), "+f"(c[3])
        : "r"(a[0]), "r"(a[1]), "r"(a[2]), "r"(a[3]), "r"(b[0]), "r"(b[1]));
}

__device__ __forceinline__ float ex2f(float x) {
    float y;
    asm("ex2.approx.ftz.f32 %0, %1;" : "=f"(y) : "f"(x));
    return y;
}

// ---------------------------------------------------------------------------
// Conversion kernels
// ---------------------------------------------------------------------------
__global__ __launch_bounds__(256) void to_f16_kernel(
    const float* __restrict__ src, __half* __restrict__ dst, int n4)
{
    int i = blockIdx.x * blockDim.x + threadIdx.x;
    if (i >= n4) return;
    float4 v = reinterpret_cast<const float4*>(src)[i];
    ushort4 hv;
    hv.x = __half_as_ushort(__float2half_rn(v.x));
    hv.y = __half_as_ushort(__float2half_rn(v.y));
    hv.z = __half_as_ushort(__float2half_rn(v.z));
    hv.w = __half_as_ushort(__float2half_rn(v.w));
    reinterpret_cast<ushort4*>(dst)[i] = hv;
}

// dict [N_ATOMS][DM] fp32 -> DTf [DM][N_ATOMS] fp16
__global__ __launch_bounds__(256) void transpose_f16_kernel(
    const float* __restrict__ dict, __half* __restrict__ DTf)
{
    __shared__ float t[32][33];
    const int bx = blockIdx.x;
    const int by = blockIdx.y;
    const int tx = threadIdx.x;
    const int ty = threadIdx.y;
    #pragma unroll
    for (int k = 0; k < 32; k += 8)
        t[ty + k][tx] = dict[(size_t)(by * 32 + ty + k) * DM + bx * 32 + tx];
    __syncthreads();
    #pragma unroll
    for (int k = 0; k < 32; k += 8) {
        size_t o = (size_t)(bx * 32 + ty + k) * N_ATOMS + by * 32 + tx;
        DTf[o] = __float2half_rn(t[tx][ty + k]);
    }
}

// ---------------------------------------------------------------------------
// Unified 1-term fp16 GEMM via ldmatrix + mma.sync, 4-stage cp.async pipe.
// out tile 128x128 = A[M,K] · B[N,K]^T
// MASK=true : out is __half, masked -> NEG_H, scaled by LOG2E (scores)
// MASK=false: out is float, row scaled by invp[row] (recon)
// 128 threads = 4 warps (2x2) of 64x64, BK=32.
// smem rows: 64B data + 16B pad (80B) — conflict-free LDSM phases.
// ---------------------------------------------------------------------------
#define ROWB     80
#define TILE_B   (128 * ROWB)          // 10240
#define STAGE    (2 * TILE_B)          // 20480
#define NSTAGES  4
#define SMEMG    (NSTAGES * STAGE)     // 81920

template <bool MASK>
__global__ __launch_bounds__(128, 2) void gemm_f16(
    const __half* __restrict__ A, const __half* __restrict__ B, int Kdim,
    const int* __restrict__ mask, const float* __restrict__ invp,
    void* __restrict__ outp, int out_ld)
{
    extern __shared__ char smem[];
    const uint32_t sbase = smem_to_u32(smem);
    const int tid  = threadIdx.x;
    const int warp = tid >> 5;
    const int lane = tid & 31;
    const int bm = blockIdx.y * 128;
    const int bn = blockIdx.x * 128;
    const int wm = (warp & 1) * 64;
    const int wn = (warp >> 1) * 64;

    // ldmatrix per-thread address components
    const int a_row = wm + (lane & 15);
    const int a_kh  = (lane >> 4) * 16;
    const int b_row = wn + ((lane >> 4) << 3) + (lane & 7);
    const int b_kh  = ((lane >> 3) & 1) * 16;

    float acc[4][8][4];
    #pragma unroll
    for (int mt = 0; mt < 4; mt++)
        #pragma unroll
        for (int nt = 0; nt < 8; nt++)
            #pragma unroll
            for (int r = 0; r < 4; r++) acc[mt][nt][r] = 0.0f;

    #define ISSUEG(cc, buf) do { \
        const int k0_ = (cc) << 5; \
        _Pragma("unroll") \
        for (int p = 0; p < 4; p++) { \
            const int v_   = tid + p * 128; \
            const int row_ = v_ >> 2; \
            const int c16_ = v_ & 3; \
            const uint32_t dst_ = sbase + (buf) * STAGE \
                                + row_ * ROWB + c16_ * 16; \
            const size_t ga_ = (size_t)(bm + row_) * Kdim + k0_ + c16_ * 8; \
            const size_t gb_ = (size_t)(bn + row_) * Kdim + k0_ + c16_ * 8; \
            CP16(dst_ + 0 * TILE_B, A + ga_); \
            CP16(dst_ + 1 * TILE_B, B + gb_); \
        } \
        CP_COMMIT(); \
    } while (0)

    ISSUEG(0, 0);
    ISSUEG(1, 1);
    ISSUEG(2, 2);

    const int NC = Kdim >> 5;
    for (int c = 0; c < NC; c++) {
        CP_WAIT2();          // chunk c resident (<=2 younger groups pending)
        __syncthreads();     // all warps past compute of chunk c-1
        if (c + 3 < NC) ISSUEG(c + 3, (c + 3) & 3);

        const uint32_t sA = sbase + (c & 3) * STAGE;
        const uint32_t sB = sA + TILE_B;

        #pragma unroll
        for (int ks = 0; ks < 2; ks++) {
            const uint32_t kb0 = ks * 32;

            uint32_t a[4][4], b[8][2];
            #pragma unroll
            for (int mt = 0; mt < 4; mt++) {
                const uint32_t ad = sA + (a_row + mt * 16) * ROWB + a_kh + kb0;
                LDSM4(a[mt][0], a[mt][1], a[mt][2], a[mt][3], ad);
            }
            #pragma unroll
            for (int p = 0; p < 4; p++) {
                const uint32_t bd = sB + (b_row + p * 16) * ROWB + b_kh + kb0;
                LDSM4(b[2 * p][0], b[2 * p][1], b[2 * p + 1][0], b[2 * p + 1][1], bd);
            }
            #pragma unroll
            for (int nt = 0; nt < 8; nt++)
                #pragma unroll
                for (int mt = 0; mt < 4; mt++)
                    mma16816_f16(acc[mt][nt], a[mt], b[nt]);
        }
    }
    #undef ISSUEG

    // Epilogue
    const int lr = lane >> 2;
    #pragma unroll
    for (int mt = 0; mt < 4; mt++) {
        #pragma unroll
        for (int half = 0; half < 2; half++) {
            const int rloc = bm + wm + mt * 16 + lr + half * 8;
            float inv = 1.0f;
            if (!MASK) inv = invp[rloc];
            const size_t rg = (size_t)rloc;
            #pragma unroll
            for (int nt = 0; nt < 8; nt++) {
                const size_t o = rg * (size_t)out_ld
                               + (bn + wn + nt * 8 + (lane & 3) * 2);
                if (MASK) {
                    int2 mv = *reinterpret_cast<const int2*>(mask + o);
                    float2 v;
                    v.x = mv.x ? acc[mt][nt][half * 2 + 0] * LOG2E : NEG_H;
                    v.y = mv.y ? acc[mt][nt][half * 2 + 1] * LOG2E : NEG_H;
                    *reinterpret_cast<__half2*>((__half*)outp + o) =
                        __float22half2_rn(v);
                } else {
                    float2 v;
                    v.x = acc[mt][nt][half * 2 + 0] * inv;
                    v.y = acc[mt][nt][half * 2 + 1] * inv;
                    *reinterpret_cast<float2*>((float*)outp + o) = v;
                }
            }
        }
    }
}

// ---------------------------------------------------------------------------
// Fused softmax over fp16 log2-scaled scores. Pass 1: top-4 + max.
// Pass 2: w = 2^(s - max), accumulate sum, write fp16 unnormalized weights.
// inv[row] = 1/sum applied in recon epilogue.
// ---------------------------------------------------------------------------
#define BETTER(v, i, V, I) ((v) > (V) || ((v) == (V) && (i) < (I)))

__global__ __launch_bounds__(256) void softmax_top4_kernel(
    const __half* __restrict__ S, __half* __restrict__ Wf,
    float* __restrict__ invp, int* __restrict__ top4)
{
    const int row = blockIdx.x;
    const __half* s = S + (size_t)row * N_ATOMS;
    const int tid = threadIdx.x;

    __shared__ float sv[4][256];
    __shared__ int   si[4][256];

    float tv[4] = {-INFINITY, -INFINITY, -INFINITY, -INFINITY};
    int   ti[4] = {0x7fffffff, 0x7fffffff, 0x7fffffff, 0x7fffffff};

    #define INS4(v, i) do { \
        float v_ = (v); int i_ = (i); \
        if (BETTER(v_, i_, tv[3], ti[3])) { \
            tv[3] = v_; ti[3] = i_; \
            if (BETTER(tv[3], ti[3], tv[2], ti[2])) { \
                float tv_ = tv[2]; int ti_ = ti[2]; \
                tv[2] = tv[3]; ti[2] = ti[3]; tv[3] = tv_; ti[3] = ti_; \
                if (BETTER(tv[2], ti[2], tv[1], ti[1])) { \
                    tv_ = tv[1]; ti_ = ti[1]; \
                    tv[1] = tv[2]; ti[1] = ti[2]; tv[2] = tv_; ti[2] = ti_; \
                    if (BETTER(tv[1], ti[1], tv[0], ti[0])) { \
                        tv_ = tv[0]; ti_ = ti[0]; \
                        tv[0] = tv[1]; ti[0] = ti[1]; tv[1] = tv_; ti[1] = ti_; \
                    } \
                } \
            } \
        } \
    } while (0)

    for (int c0 = tid * 8; c0 < N_ATOMS; c0 += 2048) {
        uint4 u = *reinterpret_cast<const uint4*>(s + c0);
        float2 f0 = __half22float2(*reinterpret_cast<__half2*>(&u.x));
        float2 f1 = __half22float2(*reinterpret_cast<__half2*>(&u.y));
        float2 f2 = __half22float2(*reinterpret_cast<__half2*>(&u.z));
        float2 f3 = __half22float2(*reinterpret_cast<__half2*>(&u.w));
        INS4(f0.x, c0 + 0); INS4(f0.y, c0 + 1);
        INS4(f1.x, c0 + 2); INS4(f1.y, c0 + 3);
        INS4(f2.x, c0 + 4); INS4(f2.y, c0 + 5);
        INS4(f3.x, c0 + 6); INS4(f3.y, c0 + 7);
    }
    #pragma unroll
    for (int j = 0; j < 4; j++) { sv[j][tid] = tv[j]; si[j][tid] = ti[j]; }
    __syncthreads();
    for (int off = 128; off > 0; off >>= 1) {
        if (tid < off) {
            #pragma unroll
            for (int j = 0; j < 4; j++) { tv[j] = sv[j][tid]; ti[j] = si[j][tid]; }
            #pragma unroll
            for (int j = 0; j < 4; j++)
                INS4(sv[j][tid + off], si[j][tid + off]);
            #pragma unroll
            for (int j = 0; j < 4; j++) { sv[j][tid] = tv[j]; si[j][tid] = ti[j]; }
        }
        __syncthreads();
    }
    #undef INS4

    const float rmax = sv[0][0];
    if (tid < 4) top4[row * 4 + tid] = si[tid][0];
    __syncthreads();

    // Exp pass: compute, write fp16 weights, accumulate sum
    __half* wf = Wf + (size_t)row * N_ATOMS;
    float lsum = 0.0f;
    for (int c0 = tid * 8; c0 < N_ATOMS; c0 += 2048) {
        uint4 u = *reinterpret_cast<const uint4*>(s + c0);
        float2 f0 = __half22float2(*reinterpret_cast<__half2*>(&u.x));
        float2 f1 = __half22float2(*reinterpret_cast<__half2*>(&u.y));
        float2 f2 = __half22float2(*reinterpret_cast<__half2*>(&u.z));
        float2 f3 = __half22float2(*reinterpret_cast<__half2*>(&u.w));
        float w0 = ex2f(f0.x - rmax), w1 = ex2f(f0.y - rmax);
        float w2 = ex2f(f1.x - rmax), w3 = ex2f(f1.y - rmax);
        float w4 = ex2f(f2.x - rmax), w5 = ex2f(f2.y - rmax);
        float w6 = ex2f(f3.x - rmax), w7 = ex2f(f3.y - rmax);
        lsum += ((w0 + w1) + (w2 + w3)) + ((w4 + w5) + (w6 + w7));
        uint4 o;
        *reinterpret_cast<__half2*>(&o.x) = __float22half2_rn(make_float2(w0, w1));
        *reinterpret_cast<__half2*>(&o.y) = __float22half2_rn(make_float2(w2, w3));
        *reinterpret_cast<__half2*>(&o.z) = __float22half2_rn(make_float2(w4, w5));
        *reinterpret_cast<__half2*>(&o.w) = __float22half2_rn(make_float2(w6, w7));
        *reinterpret_cast<uint4*>(wf + c0) = o;
    }
    sv[0][tid] = lsum;
    __syncthreads();
    for (int off = 128; off > 0; off >>= 1) {
        if (tid < off) sv[0][tid] += sv[0][tid + off];
        __syncthreads();
    }
    if (tid == 0) invp[row] = 1.0f / sv[0][0];
}

// ---------------------------------------------------------------------------
// Exact fp32 argmax rescue over 4 candidates. One warp per row.
// ---------------------------------------------------------------------------
__global__ __launch_bounds__(256) void argmax_rescue4_kernel(
    const float* __restrict__ X, const float* __restrict__ Dict,
    const int* __restrict__ mask, const int* __restrict__ top4,
    float* __restrict__ argmax_out)
{
    const int row = blockIdx.x * 8 + (threadIdx.x >> 5);
    const int lid = threadIdx.x & 31;
    int ci[4];
    #pragma unroll
    for (int j = 0; j < 4; j++) ci[j] = top4[row * 4 + j];

    const float* x = X + (size_t)row * DM;
    float sc[4] = {0.0f, 0.0f, 0.0f, 0.0f};
    for (int k = lid * 4; k < DM; k += 128) {
        float4 xv = *reinterpret_cast<const float4*>(x + k);
        #pragma unroll
        for (int j = 0; j < 4; j++) {
            float4 d = *reinterpret_cast<const float4*>(
                Dict + (size_t)ci[j] * DM + k);
            sc[j] += xv.x * d.x + xv.y * d.y + xv.z * d.z + xv.w * d.w;
        }
    }
    #pragma unroll
    for (int off = 16; off > 0; off >>= 1)
        #pragma unroll
        for (int j = 0; j < 4; j++)
            sc[j] += __shfl_xor_sync(0xffffffffu, sc[j], off);

    if (lid == 0) {
        const int* mrow = mask + (size_t)row * N_ATOMS;
        float bv = -INFINITY; int bi = 0x7fffffff;
        #pragma unroll
        for (int j = 0; j < 4; j++) {
            float v = mrow[ci[j]] ? sc[j] : -1e9f;
            if (BETTER(v, ci[j], bv, bi)) { bv = v; bi = ci[j]; }
        }
        argmax_out[row] = (float)bi;
    }
}

// ---------------------------------------------------------------------------
// Launch
// ---------------------------------------------------------------------------
extern "C" void kernel_launch(void* const* d_in, const int* in_sizes, int n_in,
                              void* d_out, int out_size)
{
    const float* X    = (const float*)d_in[0];
    const float* Dict = (const float*)d_in[1];
    const int*   mask = (const int*)d_in[2];
    float* out = (float*)d_out;

    __half *scores, *Xf, *Df, *DTf, *Wf;
    cudaGetSymbolAddress((void**)&scores, g_scores);
    cudaGetSymbolAddress((void**)&Xf, g_Xf);
    cudaGetSymbolAddress((void**)&Df, g_Df);
    cudaGetSymbolAddress((void**)&DTf, g_DTf);
    cudaGetSymbolAddress((void**)&Wf, g_Wf);
    float* invp; cudaGetSymbolAddress((void**)&invp, g_inv);
    int* top4; cudaGetSymbolAddress((void**)&top4, g_top4);

    float* recon_out  = out;
    float* argmax_out = out + (size_t)M_ROWS * DM;

    static bool attr_set = false;
    if (!attr_set) {
        cudaFuncSetAttribute(gemm_f16<true>,
                             cudaFuncAttributeMaxDynamicSharedMemorySize, SMEMG);
        cudaFuncSetAttribute(gemm_f16<false>,
                             cudaFuncAttributeMaxDynamicSharedMemorySize, SMEMG);
        attr_set = true;
    }

    // 1) fp16 conversions: X, dict (K-major), dict^T
    {
        int n4x = (M_ROWS * DM) / 4;
        to_f16_kernel<<<(n4x + 255) / 256, 256>>>(X, Xf, n4x);
        int n4d = (N_ATOMS * DM) / 4;
        to_f16_kernel<<<(n4d + 255) / 256, 256>>>(Dict, Df, n4d);
        dim3 grid(DM / 32, N_ATOMS / 32), blk(32, 8);
        transpose_f16_kernel<<<grid, blk>>>(Dict, DTf);
    }

    // 2) scores*log2e (fp16) = (Xf · Df^T)*log2e with fused mask
    {
        dim3 grid(N_ATOMS / 128, M_ROWS / 128);
        gemm_f16<true><<<grid, 128, SMEMG>>>(
            Xf, Df, DM, mask, nullptr, scores, N_ATOMS);
    }

    // 3) fused softmax: top-4, exp via MUFU, unnormalized fp16 weights + inv
    softmax_top4_kernel<<<M_ROWS, 256>>>(scores, Wf, invp, top4);

    // 4) exact fp32 argmax among the four candidates
    argmax_rescue4_kernel<<<M_ROWS / 8, 256>>>(X, Dict, mask, top4, argmax_out);

    // 5) reconstruction = (Wf · DTf) * inv[row]
    {
        dim3 grid(DM / 128, M_ROWS / 128);
        gemm_f16<false><<<grid, 128, SMEMG>>>(
            Wf, DTf, N_ATOMS, nullptr, invp, recon_out, DM);
    }
}